// round 12
// baseline (speedup 1.0000x reference)
#include <cuda_runtime.h>

// ThoughtEngine: B=8, L=1024, D=1024, H=16, HD=64, S=32, C=8. fp32.
// R12: split QKV. KV-only GEMM on critical path; Q-projection folded into the
// persistent loop kernel as extra non-barrier blocks (stream-free overlap).

#define LL (size_t)

static const size_t OFF_KVH  = 0;                              // 8192*2048
static const size_t OFF_QH   = OFF_KVH + LL 8192 * 2048;       // 8192*1024
static const size_t OFF_BUF  = OFF_QH  + LL 8192 * 1024;       // 8*32*1024
static const size_t OFF_KVB  = OFF_BUF + LL 8 * 32 * 1024;     // 8*32*2048
static const size_t OFF_CTX  = OFF_KVB + LL 8 * 32 * 2048;
static const size_t OFF_TOK  = OFF_CTX + 8192;
static const size_t OFF_TMP  = OFF_TOK + 8192;
static const size_t OFF_TMP2 = OFF_TMP + 8192;
static const size_t OFF_H1   = OFF_TMP2 + 8192;                // 8*2048
static const size_t OFF_Q    = OFF_H1 + 16384;
static const size_t OFF_AO   = OFF_Q + 8192;
static const size_t OFF_KVS  = OFF_AO + 8192;                  // 64*2048
static const size_t OFF_SSUM = OFF_KVS + 131072;               // 64*1024
static const size_t OFF_O    = OFF_SSUM + 65536;               // 8192*1024
static const size_t OFF_ATT  = OFF_O + LL 8192 * 1024;         // 8192*1024
static const size_t SCR_TOT  = OFF_ATT + LL 8192 * 1024;

__device__ __align__(16) float g_scratch[SCR_TOT];
__device__ unsigned g_bar = 0;   // monotonic ticket; participants = 256 exactly

__device__ __forceinline__ float geluf(float x) {
    return 0.5f * x * (1.0f + erff(x * 0.7071067811865475f));
}

// Grid barrier over exactly the 256 loop blocks (bid < 256).
__device__ __forceinline__ void gsync() {
    __syncthreads();
    if (threadIdx.x == 0) {
        __threadfence();
        unsigned t = atomicAdd(&g_bar, 1u);
        unsigned target = (t & ~255u) + 256u;
        while ((int)(*(volatile unsigned*)&g_bar - target) < 0) { }
        __threadfence();
    }
    __syncthreads();
}

// In-place LayerNorm of 8 rows x 1024 staged in smem. blockDim == 256.
__device__ __forceinline__ void ln_inplace(float* sA, const float* g,
                                           const float* bv, float* st) {
    int tid = threadIdx.x, lane = tid & 31, w = tid >> 5;
    float s = 0.f;
    #pragma unroll
    for (int c = lane; c < 1024; c += 32) s += sA[w * 1024 + c];
    #pragma unroll
    for (int o = 16; o; o >>= 1) s += __shfl_xor_sync(0xffffffffu, s, o);
    float mean = s * (1.0f / 1024.0f);
    float v = 0.f;
    #pragma unroll
    for (int c = lane; c < 1024; c += 32) { float d = sA[w * 1024 + c] - mean; v += d * d; }
    #pragma unroll
    for (int o = 16; o; o >>= 1) v += __shfl_xor_sync(0xffffffffu, v, o);
    if (lane == 0) { st[w] = mean; st[8 + w] = rsqrtf(v * (1.0f / 1024.0f) + 1e-5f); }
    __syncthreads();
    for (int idx = tid; idx < 8192; idx += 256) {
        int r = idx >> 10, d = idx & 1023;
        sA[idx] = (sA[idx] - st[r]) * st[8 + r] * g[d] + bv[d];
    }
    __syncthreads();
}

__global__ void mean_kernel(const float* __restrict__ hidden, float* __restrict__ ctx) {
    int b = blockIdx.y;
    int d = blockIdx.x * 256 + threadIdx.x;
    const float* p = hidden + LL b * 1048576 + d;
    float s = 0.f;
    #pragma unroll 8
    for (int l = 0; l < 1024; ++l) s += p[LL l * 1024];
    ctx[b * 1024 + d] = s * (1.0f / 1024.0f);
}

__global__ void copy_to_buf(const float* __restrict__ tok, float* __restrict__ buf, int slot) {
    int b = blockIdx.x;
    int d = blockIdx.y * 256 + threadIdx.x;
    buf[LL(b * 32 + slot) * 1024 + d] = tok[b * 1024 + d];
}

// Scalar GEMM (proven): C[M,N] = A[M,K]@B[N,K]^T + bias. BM=128 BN=64 BK=16.
__global__ __launch_bounds__(256) void sgemm(
    const float* __restrict__ A, const float* __restrict__ B,
    const float* __restrict__ bias, float* __restrict__ C,
    int M, int N, int K)
{
    __shared__ __align__(16) float As[16][128];
    __shared__ __align__(16) float Bs[16][64];
    int tid = threadIdx.x;
    int tx = tid & 15, ty = tid >> 4;
    int bm = blockIdx.y * 128, bn = blockIdx.x * 64;
    float acc[8][4];
    #pragma unroll
    for (int i = 0; i < 8; ++i)
        #pragma unroll
        for (int j = 0; j < 4; ++j) acc[i][j] = 0.f;

    for (int kk = 0; kk < K; kk += 16) {
        #pragma unroll
        for (int s = tid; s < 512; s += 256) {
            int r = s >> 2, c = (s & 3) << 2;
            int gr = bm + r;
            float4 v = make_float4(0.f, 0.f, 0.f, 0.f);
            if (gr < M) v = *reinterpret_cast<const float4*>(A + LL gr * K + kk + c);
            As[c][r] = v.x; As[c + 1][r] = v.y; As[c + 2][r] = v.z; As[c + 3][r] = v.w;
        }
        {
            int r = tid >> 2, c = (tid & 3) << 2;
            float4 v = *reinterpret_cast<const float4*>(B + LL(bn + r) * K + kk + c);
            Bs[c][r] = v.x; Bs[c + 1][r] = v.y; Bs[c + 2][r] = v.z; Bs[c + 3][r] = v.w;
        }
        __syncthreads();
        #pragma unroll
        for (int k = 0; k < 16; ++k) {
            float a[8], bb[4];
            #pragma unroll
            for (int i = 0; i < 8; ++i) a[i] = As[k][ty * 8 + i];
            #pragma unroll
            for (int j = 0; j < 4; ++j) bb[j] = Bs[k][tx * 4 + j];
            #pragma unroll
            for (int i = 0; i < 8; ++i)
                #pragma unroll
                for (int j = 0; j < 4; ++j) acc[i][j] += a[i] * bb[j];
        }
        __syncthreads();
    }
    #pragma unroll
    for (int i = 0; i < 8; ++i) {
        int row = bm + ty * 8 + i;
        if (row < M) {
            float* cr = C + LL row * N + bn + tx * 4;
            #pragma unroll
            for (int j = 0; j < 4; ++j) cr[j] = acc[i][j] + bias[bn + tx * 4 + j];
        }
    }
}

// out[b,n] = A[b,:K].W[n,:K] + bias[n], 8 rows, warp per n (Phase A tok0 only).
__global__ __launch_bounds__(256) void smallgemm8(
    const float* __restrict__ A, int K,
    const float* __restrict__ W, const float* __restrict__ bias,
    float* __restrict__ out, int N)
{
    __shared__ __align__(16) float As[8192];
    int tid = threadIdx.x, lane = tid & 31, w = tid >> 5;
    int n = blockIdx.x * 8 + w;
    float acc[8];
    #pragma unroll
    for (int b = 0; b < 8; ++b) acc[b] = 0.f;
    for (int kk = 0; kk < K; kk += 1024) {
        for (int i = tid; i < 8192; i += 256) {
            int b = i >> 10, k = i & 1023;
            As[i] = A[LL b * K + kk + k];
        }
        __syncthreads();
        const float4* wr = reinterpret_cast<const float4*>(W + LL n * K + kk);
        for (int k4 = lane; k4 < 256; k4 += 32) {
            float4 wv = wr[k4];
            #pragma unroll
            for (int b = 0; b < 8; ++b) {
                float4 av = reinterpret_cast<const float4*>(As + b * 1024)[k4];
                acc[b] += wv.x * av.x + wv.y * av.y + wv.z * av.z + wv.w * av.w;
            }
        }
        __syncthreads();
    }
    #pragma unroll
    for (int off = 16; off; off >>= 1)
        #pragma unroll
        for (int b = 0; b < 8; ++b) acc[b] += __shfl_down_sync(0xffffffffu, acc[b], off);
    if (lane == 0) {
        float bv = bias[n];
        #pragma unroll
        for (int b = 0; b < 8; ++b) out[b * N + n] = acc[b] + bv;
    }
}

// ============================================================================
// Mega kernel: bid<256 = persistent 31-step loop (ticket barrier among 256);
// bid>=256 = Q-projection GEMM tiles (qh = hidden @ wq^T + bq), no barrier.
// __launch_bounds__(256,3): 444 resident slots -> all 256 loop blocks are
// wave-1 resident (deadlock-free); ~188 slots run Q tiles concurrently.
// ============================================================================
__global__ __launch_bounds__(256, 3) void mega_kernel(
    const float* __restrict__ hidden,
    const float* __restrict__ aiw, const float* __restrict__ aib,
    const float* __restrict__ aow, const float* __restrict__ aob,
    const float* __restrict__ fw1, const float* __restrict__ fb1,
    const float* __restrict__ fw2, const float* __restrict__ fb2,
    const float* __restrict__ ln1g, const float* __restrict__ ln1b,
    const float* __restrict__ ln2g, const float* __restrict__ ln2b,
    const float* __restrict__ kvh, const float* __restrict__ tok0,
    float* qh, float* q, float* kvb, float* ao, float* tmp, float* h1,
    float* tmp2, float* buf)
{
    __shared__ __align__(16) float sA[8192];   // 32KB; gemm path aliases into it
    __shared__ float st[16];
    __shared__ float sc[1056];
    __shared__ float red[256];
    __shared__ float part[8][64];
    int tid = threadIdx.x, lane = tid & 31, w = tid >> 5;
    int bid = blockIdx.x;

    if (bid >= 256) {
        // ---------------- Q-projection GEMM tile ----------------
        int t = bid - 256;                 // 0..1023
        int bm = (t >> 4) * 128;           // M tiles: 64
        int bn = (t & 15) * 64;            // N tiles: 16
        int tx = tid & 15, ty = tid >> 4;
        float* As = sA;                    // [16][128] -> k*128 + r
        float* Bs = sA + 2048;             // [16][64]  -> k*64  + r
        float acc[8][4];
        #pragma unroll
        for (int i = 0; i < 8; ++i)
            #pragma unroll
            for (int j = 0; j < 4; ++j) acc[i][j] = 0.f;
        for (int kk = 0; kk < 1024; kk += 16) {
            #pragma unroll
            for (int s = tid; s < 512; s += 256) {
                int r = s >> 2, c = (s & 3) << 2;
                float4 v = *reinterpret_cast<const float4*>(
                    hidden + LL(bm + r) * 1024 + kk + c);
                As[c * 128 + r] = v.x; As[(c + 1) * 128 + r] = v.y;
                As[(c + 2) * 128 + r] = v.z; As[(c + 3) * 128 + r] = v.w;
            }
            {
                int r = tid >> 2, c = (tid & 3) << 2;
                float4 v = *reinterpret_cast<const float4*>(
                    aiw + LL(bn + r) * 1024 + kk + c);
                Bs[c * 64 + r] = v.x; Bs[(c + 1) * 64 + r] = v.y;
                Bs[(c + 2) * 64 + r] = v.z; Bs[(c + 3) * 64 + r] = v.w;
            }
            __syncthreads();
            #pragma unroll
            for (int k = 0; k < 16; ++k) {
                float a[8], bb[4];
                #pragma unroll
                for (int i = 0; i < 8; ++i) a[i] = As[k * 128 + ty * 8 + i];
                #pragma unroll
                for (int j = 0; j < 4; ++j) bb[j] = Bs[k * 64 + tx * 4 + j];
                #pragma unroll
                for (int i = 0; i < 8; ++i)
                    #pragma unroll
                    for (int j = 0; j < 4; ++j) acc[i][j] += a[i] * bb[j];
            }
            __syncthreads();
        }
        #pragma unroll
        for (int i = 0; i < 8; ++i) {
            float* cr = qh + LL(bm + ty * 8 + i) * 1024 + bn + tx * 4;
            #pragma unroll
            for (int j = 0; j < 4; ++j) cr[j] = acc[i][j] + aib[bn + tx * 4 + j];
        }
        return;
    }

    // ---------------- Persistent 31-step loop ----------------
    for (int i = 1; i < 32; ++i) {
        // S1: (LN2 for i>=2) + qkv of tok -> q, kvb slot i-1
        if (i == 1) {
            for (int idx = tid; idx < 8192; idx += 256) sA[idx] = tok0[idx];
            __syncthreads();
        } else {
            const float4* src4 = reinterpret_cast<const float4*>(tmp2);
            for (int idx = tid; idx < 2048; idx += 256)
                reinterpret_cast<float4*>(sA)[idx] = __ldcg(src4 + idx);
            __syncthreads();
            ln_inplace(sA, ln2g, ln2b, st);
            if (bid == 0) {
                for (int idx = tid; idx < 8192; idx += 256) {
                    int b = idx >> 10, d = idx & 1023;
                    buf[LL(b * 32 + i - 1) * 1024 + d] = sA[idx];
                }
            }
        }
        int n0 = bid * 8 + w;
        float tokres[8];
        #pragma unroll
        for (int b = 0; b < 8; ++b) tokres[b] = sA[b * 1024 + n0];

        for (int n = n0; n < 3072; n += 2048) {
            const float4* wr = reinterpret_cast<const float4*>(aiw + LL n * 1024);
            float acc[8];
            #pragma unroll
            for (int b = 0; b < 8; ++b) acc[b] = 0.f;
            for (int k4 = lane; k4 < 256; k4 += 32) {
                float4 wv = wr[k4];
                #pragma unroll
                for (int b = 0; b < 8; ++b) {
                    float4 av = reinterpret_cast<const float4*>(sA + b * 1024)[k4];
                    acc[b] += wv.x * av.x + wv.y * av.y + wv.z * av.z + wv.w * av.w;
                }
            }
            #pragma unroll
            for (int off = 16; off; off >>= 1)
                #pragma unroll
                for (int b = 0; b < 8; ++b) acc[b] += __shfl_down_sync(0xffffffffu, acc[b], off);
            if (lane == 0) {
                float bv = aib[n];
                #pragma unroll
                for (int b = 0; b < 8; ++b) {
                    float v = acc[b] + bv;
                    if (n < 1024) q[b * 1024 + n] = v;
                    else kvb[LL(b * 32 + i - 1) * 2048 + (n - 1024)] = v;
                }
            }
        }
        gsync();

        // S2: attention over Lk = 1024 + i keys; blocks 0..127 = (b,h)
        if (bid < 128) {
            int b = bid >> 4, h = bid & 15;
            int Lk = 1024 + i;
            if (tid < 64) sA[tid] = __ldcg(q + b * 1024 + h * 64 + tid);
            __syncthreads();
            float lmax = -1e30f;
            for (int j = tid; j < Lk; j += 256) {
                float s = 0.f;
                const float4* q4 = reinterpret_cast<const float4*>(sA);
                if (j < 1024) {
                    const float4* k4 = reinterpret_cast<const float4*>(
                        kvh + LL(b * 1024 + j) * 2048 + h * 64);
                    #pragma unroll
                    for (int d = 0; d < 16; ++d) {
                        float4 kv = k4[d], qv = q4[d];
                        s += kv.x * qv.x + kv.y * qv.y + kv.z * qv.z + kv.w * qv.w;
                    }
                } else {
                    const float4* k4 = reinterpret_cast<const float4*>(
                        kvb + LL(b * 32 + j - 1024) * 2048 + h * 64);
                    #pragma unroll
                    for (int d = 0; d < 16; ++d) {
                        float4 kv = __ldcg(k4 + d);
                        float4 qv = q4[d];
                        s += kv.x * qv.x + kv.y * qv.y + kv.z * qv.z + kv.w * qv.w;
                    }
                }
                s *= 0.125f;
                sc[j] = s;
                lmax = fmaxf(lmax, s);
            }
            red[tid] = lmax; __syncthreads();
            for (int o = 128; o; o >>= 1) { if (tid < o) red[tid] = fmaxf(red[tid], red[tid + o]); __syncthreads(); }
            float m = red[0];
            __syncthreads();
            float lsum = 0.f;
            for (int j = tid; j < Lk; j += 256) { float p = __expf(sc[j] - m); sc[j] = p; lsum += p; }
            red[tid] = lsum; __syncthreads();
            for (int o = 128; o; o >>= 1) { if (tid < o) red[tid] += red[tid + o]; __syncthreads(); }
            float inv = 1.0f / red[0];

            int g = tid >> 5, d0 = (tid & 31) * 2;
            float ax = 0.f, ay = 0.f;
            for (int j = g; j < Lk; j += 8) {
                float2 v;
                if (j < 1024)
                    v = *reinterpret_cast<const float2*>(
                        kvh + LL(b * 1024 + j) * 2048 + 1024 + h * 64 + d0);
                else
                    v = __ldcg(reinterpret_cast<const float2*>(
                        kvb + LL(b * 32 + j - 1024) * 2048 + 1024 + h * 64 + d0));
                float p = sc[j];
                ax += p * v.x; ay += p * v.y;
            }
            part[g][d0] = ax; part[g][d0 + 1] = ay;
            __syncthreads();
            if (tid < 64) {
                float s = 0.f;
                #pragma unroll
                for (int gg = 0; gg < 8; ++gg) s += part[gg][tid];
                ao[b * 1024 + h * 64 + tid] = s * inv;
            }
        }
        gsync();

        // S3: out-proj + residual -> tmp (blocks 0..127)
        if (bid < 128) {
            const float4* src4 = reinterpret_cast<const float4*>(ao);
            for (int idx = tid; idx < 2048; idx += 256)
                reinterpret_cast<float4*>(sA)[idx] = __ldcg(src4 + idx);
            __syncthreads();
            int n = n0;
            const float4* wr = reinterpret_cast<const float4*>(aow + LL n * 1024);
            float acc[8];
            #pragma unroll
            for (int b = 0; b < 8; ++b) acc[b] = 0.f;
            for (int k4 = lane; k4 < 256; k4 += 32) {
                float4 wv = wr[k4];
                #pragma unroll
                for (int b = 0; b < 8; ++b) {
                    float4 av = reinterpret_cast<const float4*>(sA + b * 1024)[k4];
                    acc[b] += wv.x * av.x + wv.y * av.y + wv.z * av.z + wv.w * av.w;
                }
            }
            #pragma unroll
            for (int off = 16; off; off >>= 1)
                #pragma unroll
                for (int b = 0; b < 8; ++b) acc[b] += __shfl_down_sync(0xffffffffu, acc[b], off);
            if (lane == 0) {
                float bv = aob[n];
                #pragma unroll
                for (int b = 0; b < 8; ++b)
                    tmp[b * 1024 + n] = acc[b] + bv + tokres[b];
            }
        }
        gsync();

        // S4: LN1 + FFN1(gelu) -> h1 (all 256 blocks; n = n0 < 2048)
        {
            const float4* src4 = reinterpret_cast<const float4*>(tmp);
            for (int idx = tid; idx < 2048; idx += 256)
                reinterpret_cast<float4*>(sA)[idx] = __ldcg(src4 + idx);
            __syncthreads();
            ln_inplace(sA, ln1g, ln1b, st);
        }
        float resv[8];
        #pragma unroll
        for (int b = 0; b < 8; ++b) resv[b] = sA[b * 1024 + (n0 & 1023)];
        {
            int n = n0;
            const float4* wr = reinterpret_cast<const float4*>(fw1 + LL n * 1024);
            float acc[8];
            #pragma unroll
            for (int b = 0; b < 8; ++b) acc[b] = 0.f;
            for (int k4 = lane; k4 < 256; k4 += 32) {
                float4 wv = wr[k4];
                #pragma unroll
                for (int b = 0; b < 8; ++b) {
                    float4 av = reinterpret_cast<const float4*>(sA + b * 1024)[k4];
                    acc[b] += wv.x * av.x + wv.y * av.y + wv.z * av.z + wv.w * av.w;
                }
            }
            #pragma unroll
            for (int off = 16; off; off >>= 1)
                #pragma unroll
                for (int b = 0; b < 8; ++b) acc[b] += __shfl_down_sync(0xffffffffu, acc[b], off);
            if (lane == 0) {
                float bv = fb1[n];
                #pragma unroll
                for (int b = 0; b < 8; ++b) h1[b * 2048 + n] = geluf(acc[b] + bv);
            }
        }
        gsync();

        // S5: FFN2 + residual -> tmp2 (blocks 0..127)
        if (bid < 128) {
            float acc[8];
            #pragma unroll
            for (int b = 0; b < 8; ++b) acc[b] = 0.f;
            int n = n0;
            for (int kk = 0; kk < 2048; kk += 1024) {
                const float4* h4 = reinterpret_cast<const float4*>(h1);
                for (int idx = tid; idx < 2048; idx += 256) {
                    int b = idx >> 8, k4i = idx & 255;
                    reinterpret_cast<float4*>(sA)[idx] =
                        __ldcg(h4 + b * 512 + (kk >> 2) + k4i);
                }
                __syncthreads();
                const float4* wr = reinterpret_cast<const float4*>(fw2 + LL n * 2048 + kk);
                for (int k4 = lane; k4 < 256; k4 += 32) {
                    float4 wv = wr[k4];
                    #pragma unroll
                    for (int b = 0; b < 8; ++b) {
                        float4 av = reinterpret_cast<const float4*>(sA + b * 1024)[k4];
                        acc[b] += wv.x * av.x + wv.y * av.y + wv.z * av.z + wv.w * av.w;
                    }
                }
                __syncthreads();
            }
            #pragma unroll
            for (int off = 16; off; off >>= 1)
                #pragma unroll
                for (int b = 0; b < 8; ++b) acc[b] += __shfl_down_sync(0xffffffffu, acc[b], off);
            if (lane == 0) {
                float bv = fb2[n];
                #pragma unroll
                for (int b = 0; b < 8; ++b)
                    tmp2[b * 1024 + n] = acc[b] + bv + resv[b];
            }
        }
        gsync();
    }
}

// Standalone LN of 8 rows (final step's LN2 -> buf slot 31).
__global__ void ln8(const float* __restrict__ x, const float* __restrict__ gg,
                    const float* __restrict__ bb, float* __restrict__ out,
                    float* __restrict__ buf, int slot)
{
    int b = blockIdx.x, tid = threadIdx.x;
    __shared__ float red[256];
    const float* xr = x + b * 1024;
    float vals[4]; float s = 0.f;
    #pragma unroll
    for (int i = 0; i < 4; ++i) { vals[i] = xr[tid + 256 * i]; s += vals[i]; }
    red[tid] = s; __syncthreads();
    for (int o = 128; o; o >>= 1) { if (tid < o) red[tid] += red[tid + o]; __syncthreads(); }
    float mean = red[0] * (1.0f / 1024.0f);
    __syncthreads();
    float v = 0.f;
    #pragma unroll
    for (int i = 0; i < 4; ++i) { float dd = vals[i] - mean; v += dd * dd; }
    red[tid] = v; __syncthreads();
    for (int o = 128; o; o >>= 1) { if (tid < o) red[tid] += red[tid + o]; __syncthreads(); }
    float inv = rsqrtf(red[0] * (1.0f / 1024.0f) + 1e-5f);
    #pragma unroll
    for (int i = 0; i < 4; ++i) {
        int d = tid + 256 * i;
        float y = (vals[i] - mean) * inv * gg[d] + bb[d];
        out[b * 1024 + d] = y;
        if (buf) buf[LL(b * 32 + slot) * 1024 + d] = y;
    }
}

// cond[l] = LN(hidden[l] + att[l])
__global__ void ln_big(const float* __restrict__ hidden, const float* __restrict__ att,
                       const float* __restrict__ gg, const float* __restrict__ bb,
                       float* __restrict__ out)
{
    int l = blockIdx.x, tid = threadIdx.x;
    __shared__ float red[256];
    const float* hr = hidden + LL l * 1024;
    const float* ar = att + LL l * 1024;
    float vals[4]; float s = 0.f;
    #pragma unroll
    for (int i = 0; i < 4; ++i) { vals[i] = hr[tid + 256 * i] + ar[tid + 256 * i]; s += vals[i]; }
    red[tid] = s; __syncthreads();
    for (int o = 128; o; o >>= 1) { if (tid < o) red[tid] += red[tid + o]; __syncthreads(); }
    float mean = red[0] * (1.0f / 1024.0f);
    __syncthreads();
    float v = 0.f;
    #pragma unroll
    for (int i = 0; i < 4; ++i) { float dd = vals[i] - mean; v += dd * dd; }
    red[tid] = v; __syncthreads();
    for (int o = 128; o; o >>= 1) { if (tid < o) red[tid] += red[tid + o]; __syncthreads(); }
    float inv = rsqrtf(red[0] * (1.0f / 1024.0f) + 1e-5f);
    #pragma unroll
    for (int i = 0; i < 4; ++i) {
        int d = tid + 256 * i;
        out[LL l * 1024 + d] = (vals[i] - mean) * inv * gg[d] + bb[d];
    }
}

// ssum[b,c,:] = softmax_s(comp_q[c].thoughts[b,s] / 32) @ thoughts[b]
__global__ __launch_bounds__(256) void comp_kernel(
    const float* __restrict__ comp_q, const float* __restrict__ thoughts,
    float* __restrict__ ssum)
{
    int b = blockIdx.x >> 3, c = blockIdx.x & 7;
    __shared__ float sc[32];
    __shared__ float pr[32];
    int tid = threadIdx.x, lane = tid & 31, w = tid >> 5;
    const float* qr = comp_q + c * 1024;
    #pragma unroll
    for (int si = 0; si < 4; ++si) {
        int s = w * 4 + si;
        const float* t = thoughts + LL(b * 32 + s) * 1024;
        float acc = 0.f;
        for (int k = lane; k < 1024; k += 32) acc += qr[k] * t[k];
        #pragma unroll
        for (int o = 16; o; o >>= 1) acc += __shfl_down_sync(0xffffffffu, acc, o);
        if (lane == 0) sc[s] = acc * (1.0f / 32.0f);
    }
    __syncthreads();
    if (tid == 0) {
        float m = -1e30f;
        for (int s = 0; s < 32; ++s) m = fmaxf(m, sc[s]);
        float S = 0.f;
        for (int s = 0; s < 32; ++s) { float p = __expf(sc[s] - m); pr[s] = p; S += p; }
        float iv = 1.0f / S;
        for (int s = 0; s < 32; ++s) pr[s] *= iv;
    }
    __syncthreads();
    for (int d = tid; d < 1024; d += 256) {
        float acc = 0.f;
        #pragma unroll
        for (int s = 0; s < 32; ++s) acc += pr[s] * thoughts[LL(b * 32 + s) * 1024 + d];
        ssum[LL(b * 8 + c) * 1024 + d] = acc;
    }
}

// Final MHA: one warp per (row l, head h); 8 keys from kvs (k|v rows).
__global__ __launch_bounds__(256) void final_attn(
    const float* __restrict__ qh, const float* __restrict__ kvs,
    float* __restrict__ o)
{
    int tid = threadIdx.x, lane = tid & 31, w = tid >> 5;
    int pair = blockIdx.x * 8 + w;
    int l = pair >> 4, h = pair & 15;
    int b = l >> 10;
    float2 qv = reinterpret_cast<const float2*>(qh + LL l * 1024 + h * 64)[lane];
    float s[8];
    #pragma unroll
    for (int ks = 0; ks < 8; ++ks) {
        float2 kv = reinterpret_cast<const float2*>(kvs + LL(b * 8 + ks) * 2048 + h * 64)[lane];
        float p = qv.x * kv.x + qv.y * kv.y;
        #pragma unroll
        for (int off = 16; off; off >>= 1) p += __shfl_xor_sync(0xffffffffu, p, off);
        s[ks] = p * 0.125f;
    }
    float m = s[0];
    #pragma unroll
    for (int ks = 1; ks < 8; ++ks) m = fmaxf(m, s[ks]);
    float sum = 0.f;
    #pragma unroll
    for (int ks = 0; ks < 8; ++ks) { s[ks] = __expf(s[ks] - m); sum += s[ks]; }
    float inv = 1.0f / sum;
    float o0 = 0.f, o1 = 0.f;
    #pragma unroll
    for (int ks = 0; ks < 8; ++ks) {
        float2 vv = reinterpret_cast<const float2*>(kvs + LL(b * 8 + ks) * 2048 + 1024 + h * 64)[lane];
        o0 += s[ks] * vv.x; o1 += s[ks] * vv.y;
    }
    float2 ov; ov.x = o0 * inv; ov.y = o1 * inv;
    reinterpret_cast<float2*>(o + LL l * 1024 + h * 64)[lane] = ov;
}

extern "C" void kernel_launch(void* const* d_in, const int* in_sizes, int n_in,
                              void* d_out, int out_size) {
    (void)in_sizes; (void)n_in; (void)out_size;
    const float* hidden = (const float*)d_in[0];
    const float* tpw    = (const float*)d_in[1];
    const float* tpb    = (const float*)d_in[2];
    const float* ln1g   = (const float*)d_in[3];
    const float* ln1b   = (const float*)d_in[4];
    const float* ln2g   = (const float*)d_in[5];
    const float* ln2b   = (const float*)d_in[6];
    const float* aiw    = (const float*)d_in[7];
    const float* aib    = (const float*)d_in[8];
    const float* aow    = (const float*)d_in[9];
    const float* aob    = (const float*)d_in[10];
    const float* fw1    = (const float*)d_in[11];
    const float* fb1    = (const float*)d_in[12];
    const float* fw2    = (const float*)d_in[13];
    const float* fb2    = (const float*)d_in[14];
    const float* cq     = (const float*)d_in[15];
    const float* cw     = (const float*)d_in[16];
    const float* cb     = (const float*)d_in[17];
    float* out = (float*)d_out;

    float* S;
    cudaGetSymbolAddress((void**)&S, g_scratch);
    float* KVH  = S + OFF_KVH;
    float* QH   = S + OFF_QH;
    float* BUF  = S + OFF_BUF;
    float* KVB  = S + OFF_KVB;
    float* CTX  = S + OFF_CTX;
    float* TOK  = S + OFF_TOK;
    float* TMP  = S + OFF_TMP;
    float* TMP2 = S + OFF_TMP2;
    float* H1   = S + OFF_H1;
    float* Q    = S + OFF_Q;
    float* AO   = S + OFF_AO;
    float* KVS  = S + OFF_KVS;
    float* SSUM = S + OFF_SSUM;
    float* O    = S + OFF_O;
    float* ATT  = S + OFF_ATT;
    float* SUMM = out + LL 8192 * 1024;   // (8,8,1024) tail of output

    // Phase A: KV-only projection on the critical path
    mean_kernel<<<dim3(4, 8), 256>>>(hidden, CTX);
    smallgemm8<<<128, 256>>>(CTX, 1024, tpw, tpb, TOK, 1024);
    copy_to_buf<<<dim3(8, 4), 256>>>(TOK, BUF, 0);
    sgemm<<<dim3(32, 64), 256>>>(hidden, aiw + LL 1024 * 1024, aib + 1024,
                                 KVH, 8192, 2048, 1024);

    // Phase B: persistent loop (256 blocks) + overlapped Q-GEMM (1024 blocks)
    mega_kernel<<<1280, 256>>>(hidden, aiw, aib, aow, aob, fw1, fb1, fw2, fb2,
                               ln1g, ln1b, ln2g, ln2b, KVH, TOK,
                               QH, Q, KVB, AO, TMP, H1, TMP2, BUF);
    // Final LN2 -> buf[:,31]
    ln8<<<8, 256>>>(TMP2, ln2g, ln2b, TOK, BUF, 31);

    // Phase C
    comp_kernel<<<64, 256>>>(cq, BUF, SSUM);
    sgemm<<<dim3(16, 1), 256>>>(SSUM, cw, cb, SUMM, 64, 1024, 1024);
    sgemm<<<dim3(32, 1), 256>>>(SUMM, aiw + LL 1024 * 1024, aib + 1024, KVS, 64, 2048, 1024);
    final_attn<<<16384, 256>>>(QH, KVS, O);
    sgemm<<<dim3(16, 64), 256>>>(O, aow, aob, ATT, 8192, 1024, 1024);
    ln_big<<<8192, 256>>>(hidden, ATT, ln1g, ln1b, out);
}

// round 14
// speedup vs baseline: 1.3354x; 1.3354x over previous
#include <cuda_runtime.h>
#include <cuda_bf16.h>
#include <cstdint>

// ThoughtEngine: B=8, L=1024, D=1024, H=16, HD=64, S=32, C=8. fp32.
// R14 = R10 champion topology + mma.sync (HMMA) bf16-split GEMM for the two
// big GEMMs. tcgen05 is unavailable (harness PTX targets sm_103, not sm_103a);
// mma.sync.m16n8k16 bf16 + ldmatrix are baseline sm_80/75 and legal.
// fp32 emulation: x = hi + lo (bf16); D += Ahi*Bhi + Ahi*Blo + Alo*Bhi.

#define LL (size_t)

static const size_t OFF_QKVH = 0;                              // 8192*3072
static const size_t OFF_BUF  = OFF_QKVH + LL 8192 * 3072;      // 8*32*1024
static const size_t OFF_KVB  = OFF_BUF  + LL 8 * 32 * 1024;    // 8*32*2048
static const size_t OFF_CTX  = OFF_KVB  + LL 8 * 32 * 2048;
static const size_t OFF_TOK  = OFF_CTX + 8192;
static const size_t OFF_TMP  = OFF_TOK + 8192;
static const size_t OFF_TMP2 = OFF_TMP + 8192;
static const size_t OFF_H1   = OFF_TMP2 + 8192;                // 8*2048
static const size_t OFF_Q    = OFF_H1 + 16384;
static const size_t OFF_AO   = OFF_Q + 8192;
static const size_t OFF_KVS  = OFF_AO + 8192;                  // 64*2048
static const size_t OFF_SSUM = OFF_KVS + 131072;               // 64*1024
static const size_t OFF_O    = OFF_SSUM + 65536;               // 8192*1024
static const size_t OFF_ATT  = OFF_O + LL 8192 * 1024;         // 8192*1024
static const size_t SCR_TOT  = OFF_ATT + LL 8192 * 1024;

__device__ __align__(16) float g_scratch[SCR_TOT];

// bf16 hi/lo pairs (pre-converted operands for the mma GEMMs)
static const size_t BHHI  = 0;                                 // hidden hi 8192*1024
static const size_t BHLO  = BHHI + LL 8388608;
static const size_t BWIHI = BHLO + LL 8388608;                 // attn_in_w 3072*1024
static const size_t BWILO = BWIHI + LL 3145728;
static const size_t BWOHI = BWILO + LL 3145728;                // attn_out_w 1024*1024
static const size_t BWOLO = BWOHI + LL 1048576;
static const size_t BOHI  = BWOLO + LL 1048576;                // O 8192*1024
static const size_t BOLO  = BOHI + LL 8388608;
static const size_t BF_TOT = BOLO + LL 8388608;

__device__ __align__(16) __nv_bfloat16 g_bf[BF_TOT];

__device__ __forceinline__ float geluf(float x) {
    return 0.5f * x * (1.0f + erff(x * 0.7071067811865475f));
}

__device__ __forceinline__ uint32_t smem_u32(const void* p) {
    uint32_t a;
    asm("{ .reg .u64 t; cvta.to.shared.u64 t, %1; cvt.u32.u64 %0, t; }"
        : "=r"(a) : "l"(p));
    return a;
}

__device__ __forceinline__ void ldsm_x4(uint32_t* r, uint32_t addr) {
    asm volatile("ldmatrix.sync.aligned.m8n8.x4.shared.b16 {%0,%1,%2,%3}, [%4];"
        : "=r"(r[0]), "=r"(r[1]), "=r"(r[2]), "=r"(r[3]) : "r"(addr));
}

__device__ __forceinline__ void mma16816(float* c, const uint32_t* a, const uint32_t* b) {
    asm volatile("mma.sync.aligned.m16n8k16.row.col.f32.bf16.bf16.f32 "
        "{%0,%1,%2,%3}, {%4,%5,%6,%7}, {%8,%9}, {%0,%1,%2,%3};"
        : "+f"(c[0]), "+f"(c[1]), "+f"(c[2]), "+f"(c[3])
        : "r"(a[0]), "r"(a[1]), "r"(a[2]), "r"(a[3]), "r"(b[0]), "r"(b[1]));
}

// x -> (hi, lo) bf16 pair, 4 floats per thread.
__global__ void cvt_pair(const float* __restrict__ x, __nv_bfloat16* __restrict__ hi,
                         __nv_bfloat16* __restrict__ lo, int n4) {
    int i = blockIdx.x * 256 + threadIdx.x;
    if (i >= n4) return;
    float4 v = reinterpret_cast<const float4*>(x)[i];
    float f[4] = {v.x, v.y, v.z, v.w};
    uint32_t hs[4], ls[4];
    #pragma unroll
    for (int j = 0; j < 4; ++j) {
        __nv_bfloat16 h = __float2bfloat16_rn(f[j]);
        hs[j] = (uint32_t)__bfloat16_as_ushort(h);
        ls[j] = (uint32_t)__bfloat16_as_ushort(
            __float2bfloat16_rn(f[j] - __bfloat162float(h)));
    }
    uint2 hv, lv;
    hv.x = hs[0] | (hs[1] << 16); hv.y = hs[2] | (hs[3] << 16);
    lv.x = ls[0] | (ls[1] << 16); lv.y = ls[2] | (ls[3] << 16);
    reinterpret_cast<uint2*>(hi)[i] = hv;
    reinterpret_cast<uint2*>(lo)[i] = lv;
}

// ============================================================================
// mmagemm: C[128·by+:128, 64·bx+:64] = A@B^T + bias, fp32 via bf16 hi/lo split.
// A[M,K], B[N,K] bf16 row-major (hi/lo pairs), K multiple of 32.
// 256 threads = 8 warps in 4(M)x2(N); each warp 32x32 via m16n8k16 frags.
// ============================================================================
__global__ __launch_bounds__(256) void mmagemm(
    const __nv_bfloat16* __restrict__ Ahi, const __nv_bfloat16* __restrict__ Alo,
    const __nv_bfloat16* __restrict__ Bhi, const __nv_bfloat16* __restrict__ Blo,
    const float* __restrict__ bias, float* __restrict__ C, int N, int K)
{
    __shared__ __align__(16) __nv_bfloat16 sAh[128][40];  // pad 40 -> 80B rows
    __shared__ __align__(16) __nv_bfloat16 sAl[128][40];  // (16B-mult, 20-bank stride)
    __shared__ __align__(16) __nv_bfloat16 sBh[64][40];
    __shared__ __align__(16) __nv_bfloat16 sBl[64][40];
    int tid = threadIdx.x, lane = tid & 31, wid = tid >> 5;
    int bm = blockIdx.y * 128, bn = blockIdx.x * 64;
    int wm = (wid & 3) * 32, wn = (wid >> 2) * 32;

    float acc[2][4][4];
    #pragma unroll
    for (int mi = 0; mi < 2; ++mi)
        #pragma unroll
        for (int ni = 0; ni < 4; ++ni)
            #pragma unroll
            for (int j = 0; j < 4; ++j) acc[mi][ni][j] = 0.f;

    uint32_t sAh0 = smem_u32(sAh), sAl0 = smem_u32(sAl);
    uint32_t sBh0 = smem_u32(sBh), sBl0 = smem_u32(sBl);
    // ldmatrix per-lane offsets (bytes). A: lanes0-15 -> m rows, bit4 -> k+8.
    uint32_t aoff0 = ((wm + (lane & 15)) * 40 + ((lane & 16) >> 1)) * 2;
    uint32_t aoff1 = aoff0 + 16 * 40 * 2;
    // B: row = wn + (lane&7) + (bit4? 8), col = (bit3? 8).
    uint32_t boff0 = ((wn + (lane & 7) + ((lane & 16) >> 1)) * 40 + ((lane & 8) ? 8 : 0)) * 2;
    uint32_t boff1 = boff0 + 16 * 40 * 2;

    for (int kk = 0; kk < K; kk += 32) {
        for (int c = tid; c < 512; c += 256) {
            int r = c >> 2, cg = (c & 3) << 3;
            *reinterpret_cast<uint4*>(&sAh[r][cg]) =
                *reinterpret_cast<const uint4*>(Ahi + LL(bm + r) * K + kk + cg);
            *reinterpret_cast<uint4*>(&sAl[r][cg]) =
                *reinterpret_cast<const uint4*>(Alo + LL(bm + r) * K + kk + cg);
        }
        {
            int r = tid >> 2, cg = (tid & 3) << 3;
            *reinterpret_cast<uint4*>(&sBh[r][cg]) =
                *reinterpret_cast<const uint4*>(Bhi + LL(bn + r) * K + kk + cg);
            *reinterpret_cast<uint4*>(&sBl[r][cg]) =
                *reinterpret_cast<const uint4*>(Blo + LL(bn + r) * K + kk + cg);
        }
        __syncthreads();
        #pragma unroll
        for (int k16 = 0; k16 < 2; ++k16) {
            uint32_t kb = (uint32_t)(k16 * 32);   // 16 bf16 = 32 bytes
            uint32_t ah[2][4], al[2][4], bh[4][2], bl[4][2], t[4];
            ldsm_x4(ah[0], sAh0 + aoff0 + kb);
            ldsm_x4(ah[1], sAh0 + aoff1 + kb);
            ldsm_x4(al[0], sAl0 + aoff0 + kb);
            ldsm_x4(al[1], sAl0 + aoff1 + kb);
            ldsm_x4(t, sBh0 + boff0 + kb);
            bh[0][0] = t[0]; bh[0][1] = t[1]; bh[1][0] = t[2]; bh[1][1] = t[3];
            ldsm_x4(t, sBh0 + boff1 + kb);
            bh[2][0] = t[0]; bh[2][1] = t[1]; bh[3][0] = t[2]; bh[3][1] = t[3];
            ldsm_x4(t, sBl0 + boff0 + kb);
            bl[0][0] = t[0]; bl[0][1] = t[1]; bl[1][0] = t[2]; bl[1][1] = t[3];
            ldsm_x4(t, sBl0 + boff1 + kb);
            bl[2][0] = t[0]; bl[2][1] = t[1]; bl[3][0] = t[2]; bl[3][1] = t[3];
            #pragma unroll
            for (int mi = 0; mi < 2; ++mi)
                #pragma unroll
                for (int ni = 0; ni < 4; ++ni) {
                    mma16816(acc[mi][ni], ah[mi], bh[ni]);
                    mma16816(acc[mi][ni], ah[mi], bl[ni]);
                    mma16816(acc[mi][ni], al[mi], bh[ni]);
                }
        }
        __syncthreads();
    }

    int g = lane >> 2, tq = lane & 3;
    #pragma unroll
    for (int mi = 0; mi < 2; ++mi)
        #pragma unroll
        for (int ni = 0; ni < 4; ++ni) {
            int row0 = bm + wm + mi * 16 + g;
            int col = bn + wn + ni * 8 + tq * 2;
            float b0 = bias[col], b1 = bias[col + 1];
            C[LL row0 * N + col]           = acc[mi][ni][0] + b0;
            C[LL row0 * N + col + 1]       = acc[mi][ni][1] + b1;
            C[LL(row0 + 8) * N + col]      = acc[mi][ni][2] + b0;
            C[LL(row0 + 8) * N + col + 1]  = acc[mi][ni][3] + b1;
        }
}

// ============================== misc kernels ================================

__global__ void mean_kernel(const float* __restrict__ hidden, float* __restrict__ ctx) {
    int b = blockIdx.y;
    int d = blockIdx.x * 256 + threadIdx.x;
    const float* p = hidden + LL b * 1048576 + d;
    float s = 0.f;
    #pragma unroll 8
    for (int l = 0; l < 1024; ++l) s += p[LL l * 1024];
    ctx[b * 1024 + d] = s * (1.0f / 1024.0f);
}

__global__ void copy_to_buf(const float* __restrict__ tok, float* __restrict__ buf, int slot) {
    int b = blockIdx.x;
    int d = blockIdx.y * 256 + threadIdx.x;
    buf[LL(b * 32 + slot) * 1024 + d] = tok[b * 1024 + d];
}

// Scalar GEMM (small phase-C GEMMs only).
__global__ __launch_bounds__(256) void sgemm(
    const float* __restrict__ A, const float* __restrict__ B,
    const float* __restrict__ bias, float* __restrict__ C,
    int M, int N, int K)
{
    __shared__ __align__(16) float As[16][128];
    __shared__ __align__(16) float Bs[16][64];
    int tid = threadIdx.x;
    int tx = tid & 15, ty = tid >> 4;
    int bm = blockIdx.y * 128, bn = blockIdx.x * 64;
    float acc[8][4];
    #pragma unroll
    for (int i = 0; i < 8; ++i)
        #pragma unroll
        for (int j = 0; j < 4; ++j) acc[i][j] = 0.f;

    for (int kk = 0; kk < K; kk += 16) {
        #pragma unroll
        for (int s = tid; s < 512; s += 256) {
            int r = s >> 2, c = (s & 3) << 2;
            int gr = bm + r;
            float4 v = make_float4(0.f, 0.f, 0.f, 0.f);
            if (gr < M) v = *reinterpret_cast<const float4*>(A + LL gr * K + kk + c);
            As[c][r] = v.x; As[c + 1][r] = v.y; As[c + 2][r] = v.z; As[c + 3][r] = v.w;
        }
        {
            int r = tid >> 2, c = (tid & 3) << 2;
            float4 v = *reinterpret_cast<const float4*>(B + LL(bn + r) * K + kk + c);
            Bs[c][r] = v.x; Bs[c + 1][r] = v.y; Bs[c + 2][r] = v.z; Bs[c + 3][r] = v.w;
        }
        __syncthreads();
        #pragma unroll
        for (int k = 0; k < 16; ++k) {
            float a[8], bb[4];
            #pragma unroll
            for (int i = 0; i < 8; ++i) a[i] = As[k][ty * 8 + i];
            #pragma unroll
            for (int j = 0; j < 4; ++j) bb[j] = Bs[k][tx * 4 + j];
            #pragma unroll
            for (int i = 0; i < 8; ++i)
                #pragma unroll
                for (int j = 0; j < 4; ++j) acc[i][j] += a[i] * bb[j];
        }
        __syncthreads();
    }
    #pragma unroll
    for (int i = 0; i < 8; ++i) {
        int row = bm + ty * 8 + i;
        if (row < M) {
            float* cr = C + LL row * N + bn + tx * 4;
            #pragma unroll
            for (int j = 0; j < 4; ++j) cr[j] = acc[i][j] + bias[bn + tx * 4 + j];
        }
    }
}

// out[b,n] = A[b,:K].W[n,:K] + bias[n], 8 rows, warp per n (Phase A tok0 only).
__global__ __launch_bounds__(256) void smallgemm8(
    const float* __restrict__ A, int K,
    const float* __restrict__ W, const float* __restrict__ bias,
    float* __restrict__ out, int N)
{
    __shared__ __align__(16) float As[8192];
    int tid = threadIdx.x, lane = tid & 31, w = tid >> 5;
    int n = blockIdx.x * 8 + w;
    float acc[8];
    #pragma unroll
    for (int b = 0; b < 8; ++b) acc[b] = 0.f;
    for (int kk = 0; kk < K; kk += 1024) {
        for (int i = tid; i < 8192; i += 256) {
            int b = i >> 10, k = i & 1023;
            As[i] = A[LL b * K + kk + k];
        }
        __syncthreads();
        const float4* wr = reinterpret_cast<const float4*>(W + LL n * K + kk);
        for (int k4 = lane; k4 < 256; k4 += 32) {
            float4 wv = wr[k4];
            #pragma unroll
            for (int b = 0; b < 8; ++b) {
                float4 av = reinterpret_cast<const float4*>(As + b * 1024)[k4];
                acc[b] += wv.x * av.x + wv.y * av.y + wv.z * av.z + wv.w * av.w;
            }
        }
        __syncthreads();
    }
    #pragma unroll
    for (int off = 16; off; off >>= 1)
        #pragma unroll
        for (int b = 0; b < 8; ++b) acc[b] += __shfl_down_sync(0xffffffffu, acc[b], off);
    if (lane == 0) {
        float bv = bias[n];
        #pragma unroll
        for (int b = 0; b < 8; ++b) out[b * N + n] = acc[b] + bv;
    }
}

// In-place LayerNorm of 8 rows x 1024 staged in smem. blockDim == 256.
__device__ __forceinline__ void ln_inplace(float* sA, const float* g,
                                           const float* bv, float* st) {
    int tid = threadIdx.x, lane = tid & 31, w = tid >> 5;
    float s = 0.f;
    #pragma unroll
    for (int c = lane; c < 1024; c += 32) s += sA[w * 1024 + c];
    #pragma unroll
    for (int o = 16; o; o >>= 1) s += __shfl_xor_sync(0xffffffffu, s, o);
    float mean = s * (1.0f / 1024.0f);
    float v = 0.f;
    #pragma unroll
    for (int c = lane; c < 1024; c += 32) { float d = sA[w * 1024 + c] - mean; v += d * d; }
    #pragma unroll
    for (int o = 16; o; o >>= 1) v += __shfl_xor_sync(0xffffffffu, v, o);
    if (lane == 0) { st[w] = mean; st[8 + w] = rsqrtf(v * (1.0f / 1024.0f) + 1e-5f); }
    __syncthreads();
    for (int idx = tid; idx < 8192; idx += 256) {
        int r = idx >> 10, d = idx & 1023;
        sA[idx] = (sA[idx] - st[r]) * st[8 + r] * g[d] + bv[d];
    }
    __syncthreads();
}

// K0: (optional LN2 of pre) -> qkv. n<1024 -> q; else kvb slot step-1.
__global__ __launch_bounds__(256) void qkv_ln(
    const float* __restrict__ pre, float* tok,
    const float* __restrict__ aiw, const float* __restrict__ aib,
    const float* __restrict__ g2, const float* __restrict__ b2v,
    float* __restrict__ q, float* __restrict__ kvb, float* __restrict__ buf,
    int step, int do_ln)
{
    __shared__ __align__(16) float sA[8192];
    __shared__ float st[16];
    int tid = threadIdx.x, lane = tid & 31, w = tid >> 5;
    int bid = blockIdx.x;
    const float* src = do_ln ? pre : tok;
    for (int i = tid; i < 8192; i += 256) sA[i] = src[i];
    __syncthreads();
    if (do_ln) {
        ln_inplace(sA, g2, b2v, st);
        if (bid == 0) {
            for (int i = tid; i < 8192; i += 256) {
                tok[i] = sA[i];
                int b = i >> 10, d = i & 1023;
                buf[LL(b * 32 + step - 1) * 1024 + d] = sA[i];
            }
        }
    }
    int n = bid * 8 + w;
    const float4* wr = reinterpret_cast<const float4*>(aiw + LL n * 1024);
    float acc[8];
    #pragma unroll
    for (int b = 0; b < 8; ++b) acc[b] = 0.f;
    for (int k4 = lane; k4 < 256; k4 += 32) {
        float4 wv = wr[k4];
        #pragma unroll
        for (int b = 0; b < 8; ++b) {
            float4 av = reinterpret_cast<const float4*>(sA + b * 1024)[k4];
            acc[b] += wv.x * av.x + wv.y * av.y + wv.z * av.z + wv.w * av.w;
        }
    }
    #pragma unroll
    for (int off = 16; off; off >>= 1)
        #pragma unroll
        for (int b = 0; b < 8; ++b) acc[b] += __shfl_down_sync(0xffffffffu, acc[b], off);
    if (lane == 0) {
        float bv = aib[n];
        #pragma unroll
        for (int b = 0; b < 8; ++b) {
            float v = acc[b] + bv;
            if (n < 1024) q[b * 1024 + n] = v;
            else kvb[LL(b * 32 + step - 1) * 2048 + (n - 1024)] = v;
        }
    }
}

// K1: attention, block = (b,h), Lk = 1024 + step keys. float2 V-phase.
__global__ __launch_bounds__(256) void attn_step(
    const float* __restrict__ q, const float* __restrict__ qkvh,
    const float* __restrict__ kvb, float* __restrict__ ao, int Lk)
{
    int b = blockIdx.x >> 4, h = blockIdx.x & 15;
    __shared__ __align__(16) float sq[64];
    __shared__ float sc[1056];
    __shared__ float red[256];
    __shared__ float part[8][64];
    int tid = threadIdx.x;
    if (tid < 64) sq[tid] = q[b * 1024 + h * 64 + tid];
    __syncthreads();

    float lmax = -1e30f;
    for (int j = tid; j < Lk; j += 256) {
        const float* kr = (j < 1024)
            ? qkvh + LL(b * 1024 + j) * 3072 + 1024 + h * 64
            : kvb + LL(b * 32 + j - 1024) * 2048 + h * 64;
        const float4* k4 = reinterpret_cast<const float4*>(kr);
        const float4* q4 = reinterpret_cast<const float4*>(sq);
        float s = 0.f;
        #pragma unroll
        for (int d = 0; d < 16; ++d) {
            float4 kv = k4[d], qv = q4[d];
            s += kv.x * qv.x + kv.y * qv.y + kv.z * qv.z + kv.w * qv.w;
        }
        s *= 0.125f;
        sc[j] = s;
        lmax = fmaxf(lmax, s);
    }
    red[tid] = lmax; __syncthreads();
    for (int o = 128; o; o >>= 1) { if (tid < o) red[tid] = fmaxf(red[tid], red[tid + o]); __syncthreads(); }
    float m = red[0];
    __syncthreads();

    float lsum = 0.f;
    for (int j = tid; j < Lk; j += 256) { float p = __expf(sc[j] - m); sc[j] = p; lsum += p; }
    red[tid] = lsum; __syncthreads();
    for (int o = 128; o; o >>= 1) { if (tid < o) red[tid] += red[tid + o]; __syncthreads(); }
    float inv = 1.0f / red[0];

    int g = tid >> 5, d0 = (tid & 31) * 2;
    float ax = 0.f, ay = 0.f;
    for (int j = g; j < Lk; j += 8) {
        const float* vr = (j < 1024)
            ? qkvh + LL(b * 1024 + j) * 3072 + 2048 + h * 64
            : kvb + LL(b * 32 + j - 1024) * 2048 + 1024 + h * 64;
        float2 v = *reinterpret_cast<const float2*>(vr + d0);
        float p = sc[j];
        ax += p * v.x; ay += p * v.y;
    }
    part[g][d0] = ax; part[g][d0 + 1] = ay;
    __syncthreads();
    if (tid < 64) {
        float s = 0.f;
        #pragma unroll
        for (int gg = 0; gg < 8; ++gg) s += part[gg][tid];
        ao[b * 1024 + h * 64 + tid] = s * inv;
    }
}

// K2: tmp = ao @ aow^T + aob + tok (residual). 128 blocks.
__global__ __launch_bounds__(256) void outproj_res(
    const float* __restrict__ ao, const float* __restrict__ aow,
    const float* __restrict__ aob, const float* __restrict__ tok,
    float* __restrict__ tmp)
{
    __shared__ __align__(16) float sA[8192];
    int tid = threadIdx.x, lane = tid & 31, w = tid >> 5;
    for (int i = tid; i < 8192; i += 256) sA[i] = ao[i];
    __syncthreads();
    int n = blockIdx.x * 8 + w;
    const float4* wr = reinterpret_cast<const float4*>(aow + LL n * 1024);
    float acc[8];
    #pragma unroll
    for (int b = 0; b < 8; ++b) acc[b] = 0.f;
    for (int k4 = lane; k4 < 256; k4 += 32) {
        float4 wv = wr[k4];
        #pragma unroll
        for (int b = 0; b < 8; ++b) {
            float4 av = reinterpret_cast<const float4*>(sA + b * 1024)[k4];
            acc[b] += wv.x * av.x + wv.y * av.y + wv.z * av.z + wv.w * av.w;
        }
    }
    #pragma unroll
    for (int off = 16; off; off >>= 1)
        #pragma unroll
        for (int b = 0; b < 8; ++b) acc[b] += __shfl_down_sync(0xffffffffu, acc[b], off);
    if (lane == 0) {
        float bv = aob[n];
        #pragma unroll
        for (int b = 0; b < 8; ++b)
            tmp[b * 1024 + n] = acc[b] + bv + tok[b * 1024 + n];
    }
}

// K3: LN1(tmp) in-block -> FFN1 + gelu -> h1. bid 0 publishes tokl.
__global__ __launch_bounds__(256) void ffn1_ln(
    const float* __restrict__ tmp,
    const float* __restrict__ g1, const float* __restrict__ b1v,
    const float* __restrict__ fw1, const float* __restrict__ fb1,
    float* __restrict__ h1, float* __restrict__ tokl)
{
    __shared__ __align__(16) float sA[8192];
    __shared__ float st[16];
    int tid = threadIdx.x, lane = tid & 31, w = tid >> 5;
    int bid = blockIdx.x;
    for (int i = tid; i < 8192; i += 256) sA[i] = tmp[i];
    __syncthreads();
    ln_inplace(sA, g1, b1v, st);
    if (bid == 0)
        for (int i = tid; i < 8192; i += 256) tokl[i] = sA[i];
    int n = bid * 8 + w;
    const float4* wr = reinterpret_cast<const float4*>(fw1 + LL n * 1024);
    float acc[8];
    #pragma unroll
    for (int b = 0; b < 8; ++b) acc[b] = 0.f;
    for (int k4 = lane; k4 < 256; k4 += 32) {
        float4 wv = wr[k4];
        #pragma unroll
        for (int b = 0; b < 8; ++b) {
            float4 av = reinterpret_cast<const float4*>(sA + b * 1024)[k4];
            acc[b] += wv.x * av.x + wv.y * av.y + wv.z * av.z + wv.w * av.w;
        }
    }
    #pragma unroll
    for (int off = 16; off; off >>= 1)
        #pragma unroll
        for (int b = 0; b < 8; ++b) acc[b] += __shfl_down_sync(0xffffffffu, acc[b], off);
    if (lane == 0) {
        float bv = fb1[n];
        #pragma unroll
        for (int b = 0; b < 8; ++b) h1[b * 2048 + n] = geluf(acc[b] + bv);
    }
}

// K4: tmp2 = h1 @ fw2^T + fb2 + tokl (residual). 128 blocks.
__global__ __launch_bounds__(256) void ffn2_res(
    const float* __restrict__ h1, const float* __restrict__ fw2,
    const float* __restrict__ fb2, const float* __restrict__ tokl,
    float* __restrict__ tmp2)
{
    __shared__ __align__(16) float sA[8192];
    int tid = threadIdx.x, lane = tid & 31, w = tid >> 5;
    int n = blockIdx.x * 8 + w;
    float acc[8];
    #pragma unroll
    for (int b = 0; b < 8; ++b) acc[b] = 0.f;
    for (int kk = 0; kk < 2048; kk += 1024) {
        for (int i = tid; i < 8192; i += 256) {
            int b = i >> 10, k = i & 1023;
            sA[i] = h1[b * 2048 + kk + k];
        }
        __syncthreads();
        const float4* wr = reinterpret_cast<const float4*>(fw2 + LL n * 2048 + kk);
        for (int k4 = lane; k4 < 256; k4 += 32) {
            float4 wv = wr[k4];
            #pragma unroll
            for (int b = 0; b < 8; ++b) {
                float4 av = reinterpret_cast<const float4*>(sA + b * 1024)[k4];
                acc[b] += wv.x * av.x + wv.y * av.y + wv.z * av.z + wv.w * av.w;
            }
        }
        __syncthreads();
    }
    #pragma unroll
    for (int off = 16; off; off >>= 1)
        #pragma unroll
        for (int b = 0; b < 8; ++b) acc[b] += __shfl_down_sync(0xffffffffu, acc[b], off);
    if (lane == 0) {
        float bv = fb2[n];
        #pragma unroll
        for (int b = 0; b < 8; ++b)
            tmp2[b * 1024 + n] = acc[b] + bv + tokl[b * 1024 + n];
    }
}

__global__ void ln8(const float* __restrict__ x, const float* __restrict__ gg,
                    const float* __restrict__ bb, float* __restrict__ out,
                    float* __restrict__ buf, int slot)
{
    int b = blockIdx.x, tid = threadIdx.x;
    __shared__ float red[256];
    const float* xr = x + b * 1024;
    float vals[4]; float s = 0.f;
    #pragma unroll
    for (int i = 0; i < 4; ++i) { vals[i] = xr[tid + 256 * i]; s += vals[i]; }
    red[tid] = s; __syncthreads();
    for (int o = 128; o; o >>= 1) { if (tid < o) red[tid] += red[tid + o]; __syncthreads(); }
    float mean = red[0] * (1.0f / 1024.0f);
    __syncthreads();
    float v = 0.f;
    #pragma unroll
    for (int i = 0; i < 4; ++i) { float dd = vals[i] - mean; v += dd * dd; }
    red[tid] = v; __syncthreads();
    for (int o = 128; o; o >>= 1) { if (tid < o) red[tid] += red[tid + o]; __syncthreads(); }
    float inv = rsqrtf(red[0] * (1.0f / 1024.0f) + 1e-5f);
    #pragma unroll
    for (int i = 0; i < 4; ++i) {
        int d = tid + 256 * i;
        float y = (vals[i] - mean) * inv * gg[d] + bb[d];
        out[b * 1024 + d] = y;
        if (buf) buf[LL(b * 32 + slot) * 1024 + d] = y;
    }
}

__global__ void ln_big(const float* __restrict__ hidden, const float* __restrict__ att,
                       const float* __restrict__ gg, const float* __restrict__ bb,
                       float* __restrict__ out)
{
    int l = blockIdx.x, tid = threadIdx.x;
    __shared__ float red[256];
    const float* hr = hidden + LL l * 1024;
    const float* ar = att + LL l * 1024;
    float vals[4]; float s = 0.f;
    #pragma unroll
    for (int i = 0; i < 4; ++i) { vals[i] = hr[tid + 256 * i] + ar[tid + 256 * i]; s += vals[i]; }
    red[tid] = s; __syncthreads();
    for (int o = 128; o; o >>= 1) { if (tid < o) red[tid] += red[tid + o]; __syncthreads(); }
    float mean = red[0] * (1.0f / 1024.0f);
    __syncthreads();
    float v = 0.f;
    #pragma unroll
    for (int i = 0; i < 4; ++i) { float dd = vals[i] - mean; v += dd * dd; }
    red[tid] = v; __syncthreads();
    for (int o = 128; o; o >>= 1) { if (tid < o) red[tid] += red[tid + o]; __syncthreads(); }
    float inv = rsqrtf(red[0] * (1.0f / 1024.0f) + 1e-5f);
    #pragma unroll
    for (int i = 0; i < 4; ++i) {
        int d = tid + 256 * i;
        out[LL l * 1024 + d] = (vals[i] - mean) * inv * gg[d] + bb[d];
    }
}

__global__ __launch_bounds__(256) void comp_kernel(
    const float* __restrict__ comp_q, const float* __restrict__ thoughts,
    float* __restrict__ ssum)
{
    int b = blockIdx.x >> 3, c = blockIdx.x & 7;
    __shared__ float sc[32];
    __shared__ float pr[32];
    int tid = threadIdx.x, lane = tid & 31, w = tid >> 5;
    const float* qr = comp_q + c * 1024;
    #pragma unroll
    for (int si = 0; si < 4; ++si) {
        int s = w * 4 + si;
        const float* t = thoughts + LL(b * 32 + s) * 1024;
        float acc = 0.f;
        for (int k = lane; k < 1024; k += 32) acc += qr[k] * t[k];
        #pragma unroll
        for (int o = 16; o; o >>= 1) acc += __shfl_down_sync(0xffffffffu, acc, o);
        if (lane == 0) sc[s] = acc * (1.0f / 32.0f);
    }
    __syncthreads();
    if (tid == 0) {
        float m = -1e30f;
        for (int s = 0; s < 32; ++s) m = fmaxf(m, sc[s]);
        float S = 0.f;
        for (int s = 0; s < 32; ++s) { float p = __expf(sc[s] - m); pr[s] = p; S += p; }
        float iv = 1.0f / S;
        for (int s = 0; s < 32; ++s) pr[s] *= iv;
    }
    __syncthreads();
    for (int d = tid; d < 1024; d += 256) {
        float acc = 0.f;
        #pragma unroll
        for (int s = 0; s < 32; ++s) acc += pr[s] * thoughts[LL(b * 32 + s) * 1024 + d];
        ssum[LL(b * 8 + c) * 1024 + d] = acc;
    }
}

__global__ __launch_bounds__(256) void final_attn(
    const float* __restrict__ qkvh, const float* __restrict__ kvs,
    float* __restrict__ o)
{
    int tid = threadIdx.x, lane = tid & 31, w = tid >> 5;
    int pair = blockIdx.x * 8 + w;
    int l = pair >> 4, h = pair & 15;
    int b = l >> 10;
    float2 qv = reinterpret_cast<const float2*>(qkvh + LL l * 3072 + h * 64)[lane];
    float s[8];
    #pragma unroll
    for (int ks = 0; ks < 8; ++ks) {
        float2 kv = reinterpret_cast<const float2*>(kvs + LL(b * 8 + ks) * 2048 + h * 64)[lane];
        float p = qv.x * kv.x + qv.y * kv.y;
        #pragma unroll
        for (int off = 16; off; off >>= 1) p += __shfl_xor_sync(0xffffffffu, p, off);
        s[ks] = p * 0.125f;
    }
    float m = s[0];
    #pragma unroll
    for (int ks = 1; ks < 8; ++ks) m = fmaxf(m, s[ks]);
    float sum = 0.f;
    #pragma unroll
    for (int ks = 0; ks < 8; ++ks) { s[ks] = __expf(s[ks] - m); sum += s[ks]; }
    float inv = 1.0f / sum;
    float o0 = 0.f, o1 = 0.f;
    #pragma unroll
    for (int ks = 0; ks < 8; ++ks) {
        float2 vv = reinterpret_cast<const float2*>(kvs + LL(b * 8 + ks) * 2048 + 1024 + h * 64)[lane];
        o0 += s[ks] * vv.x; o1 += s[ks] * vv.y;
    }
    float2 ov; ov.x = o0 * inv; ov.y = o1 * inv;
    reinterpret_cast<float2*>(o + LL l * 1024 + h * 64)[lane] = ov;
}

extern "C" void kernel_launch(void* const* d_in, const int* in_sizes, int n_in,
                              void* d_out, int out_size) {
    (void)in_sizes; (void)n_in; (void)out_size;
    const float* hidden = (const float*)d_in[0];
    const float* tpw    = (const float*)d_in[1];
    const float* tpb    = (const float*)d_in[2];
    const float* ln1g   = (const float*)d_in[3];
    const float* ln1b   = (const float*)d_in[4];
    const float* ln2g   = (const float*)d_in[5];
    const float* ln2b   = (const float*)d_in[6];
    const float* aiw    = (const float*)d_in[7];
    const float* aib    = (const float*)d_in[8];
    const float* aow    = (const float*)d_in[9];
    const float* aob    = (const float*)d_in[10];
    const float* fw1    = (const float*)d_in[11];
    const float* fb1    = (const float*)d_in[12];
    const float* fw2    = (const float*)d_in[13];
    const float* fb2    = (const float*)d_in[14];
    const float* cq     = (const float*)d_in[15];
    const float* cw     = (const float*)d_in[16];
    const float* cb     = (const float*)d_in[17];
    float* out = (float*)d_out;

    float* S;
    cudaGetSymbolAddress((void**)&S, g_scratch);
    __nv_bfloat16* BF;
    cudaGetSymbolAddress((void**)&BF, g_bf);

    float* QKVH = S + OFF_QKVH;
    float* BUF  = S + OFF_BUF;
    float* KVB  = S + OFF_KVB;
    float* CTX  = S + OFF_CTX;
    float* TOK  = S + OFF_TOK;
    float* TMP  = S + OFF_TMP;
    float* TMP2 = S + OFF_TMP2;
    float* H1   = S + OFF_H1;
    float* Q    = S + OFF_Q;
    float* AO   = S + OFF_AO;
    float* KVS  = S + OFF_KVS;
    float* SSUM = S + OFF_SSUM;
    float* O    = S + OFF_O;
    float* ATT  = S + OFF_ATT;
    float* SUMM = out + LL 8192 * 1024;   // (8,8,1024) tail of output
    float* TOKL = CTX;                    // ctx is dead after tok0

    // Phase A: convert operands, then tensor-core QKV projection.
    cvt_pair<<<8192, 256>>>(hidden, BF + BHHI, BF + BHLO, 2097152);
    cvt_pair<<<3072, 256>>>(aiw, BF + BWIHI, BF + BWILO, 786432);
    cvt_pair<<<1024, 256>>>(aow, BF + BWOHI, BF + BWOLO, 262144);
    mean_kernel<<<dim3(4, 8), 256>>>(hidden, CTX);
    smallgemm8<<<128, 256>>>(CTX, 1024, tpw, tpb, TOK, 1024);
    copy_to_buf<<<dim3(8, 4), 256>>>(TOK, BUF, 0);
    mmagemm<<<dim3(48, 64), 256>>>(BF + BHHI, BF + BHLO, BF + BWIHI, BF + BWILO,
                                   aib, QKVH, 3072, 1024);

    // Phase B: 31 steps x 5 kernels
    for (int i = 1; i < 32; ++i) {
        qkv_ln<<<384, 256>>>(TMP2, TOK, aiw, aib, ln2g, ln2b, Q, KVB, BUF, i, i > 1);
        attn_step<<<128, 256>>>(Q, QKVH, KVB, AO, 1024 + i);
        outproj_res<<<128, 256>>>(AO, aow, aob, TOK, TMP);
        ffn1_ln<<<256, 256>>>(TMP, ln1g, ln1b, fw1, fb1, H1, TOKL);
        ffn2_res<<<128, 256>>>(H1, fw2, fb2, TOKL, TMP2);
    }
    ln8<<<8, 256>>>(TMP2, ln2g, ln2b, TOK, BUF, 31);

    // Phase C
    comp_kernel<<<64, 256>>>(cq, BUF, SSUM);
    sgemm<<<dim3(16, 1), 256>>>(SSUM, cw, cb, SUMM, 64, 1024, 1024);
    sgemm<<<dim3(32, 1), 256>>>(SUMM, aiw + LL 1024 * 1024, aib + 1024, KVS, 64, 2048, 1024);
    final_attn<<<16384, 256>>>(QKVH, KVS, O);
    cvt_pair<<<8192, 256>>>(O, BF + BOHI, BF + BOLO, 2097152);
    mmagemm<<<dim3(16, 64), 256>>>(BF + BOHI, BF + BOLO, BF + BWOHI, BF + BWOLO,
                                   aob, ATT, 1024, 1024);
    ln_big<<<8192, 256>>>(hidden, ATT, ln1g, ln1b, out);
}

// round 15
// speedup vs baseline: 1.3901x; 1.0409x over previous
#include <cuda_runtime.h>
#include <cuda_bf16.h>
#include <cstdint>

// ThoughtEngine: B=8, L=1024, D=1024, H=16, HD=64, S=32, C=8. fp32.
// R15 = R14 (mma.sync bf16-split big GEMMs) + split-K attention (512-block
// partial softmax + combine) + two-phase mean reduction.

#define LL (size_t)

static const size_t OFF_QKVH = 0;                              // 8192*3072
static const size_t OFF_BUF  = OFF_QKVH + LL 8192 * 3072;      // 8*32*1024
static const size_t OFF_KVB  = OFF_BUF  + LL 8 * 32 * 1024;    // 8*32*2048
static const size_t OFF_CTX  = OFF_KVB  + LL 8 * 32 * 2048;
static const size_t OFF_TOK  = OFF_CTX + 8192;
static const size_t OFF_TMP  = OFF_TOK + 8192;
static const size_t OFF_TMP2 = OFF_TMP + 8192;
static const size_t OFF_H1   = OFF_TMP2 + 8192;                // 8*2048
static const size_t OFF_Q    = OFF_H1 + 16384;
static const size_t OFF_AO   = OFF_Q + 8192;
static const size_t OFF_KVS  = OFF_AO + 8192;                  // 64*2048
static const size_t OFF_SSUM = OFF_KVS + 131072;               // 64*1024
static const size_t OFF_PO   = OFF_SSUM + 65536;               // 8*16*4*64
static const size_t OFF_PMS  = OFF_PO + 32768;                 // 8*16*4*2
static const size_t OFF_PC   = OFF_PMS + 1024;                 // 8*8*1024
static const size_t OFF_O    = OFF_PC + 65536;                 // 8192*1024
static const size_t OFF_ATT  = OFF_O + LL 8192 * 1024;         // 8192*1024
static const size_t SCR_TOT  = OFF_ATT + LL 8192 * 1024;

__device__ __align__(16) float g_scratch[SCR_TOT];

// bf16 hi/lo pairs (pre-converted operands for the mma GEMMs)
static const size_t BHHI  = 0;                                 // hidden 8192*1024
static const size_t BHLO  = BHHI + LL 8388608;
static const size_t BWIHI = BHLO + LL 8388608;                 // attn_in_w 3072*1024
static const size_t BWILO = BWIHI + LL 3145728;
static const size_t BWOHI = BWILO + LL 3145728;                // attn_out_w 1024*1024
static const size_t BWOLO = BWOHI + LL 1048576;
static const size_t BOHI  = BWOLO + LL 1048576;                // O 8192*1024
static const size_t BOLO  = BOHI + LL 8388608;
static const size_t BF_TOT = BOLO + LL 8388608;

__device__ __align__(16) __nv_bfloat16 g_bf[BF_TOT];

__device__ __forceinline__ float geluf(float x) {
    return 0.5f * x * (1.0f + erff(x * 0.7071067811865475f));
}

__device__ __forceinline__ uint32_t smem_u32(const void* p) {
    uint32_t a;
    asm("{ .reg .u64 t; cvta.to.shared.u64 t, %1; cvt.u32.u64 %0, t; }"
        : "=r"(a) : "l"(p));
    return a;
}

__device__ __forceinline__ void ldsm_x4(uint32_t* r, uint32_t addr) {
    asm volatile("ldmatrix.sync.aligned.m8n8.x4.shared.b16 {%0,%1,%2,%3}, [%4];"
        : "=r"(r[0]), "=r"(r[1]), "=r"(r[2]), "=r"(r[3]) : "r"(addr));
}

__device__ __forceinline__ void mma16816(float* c, const uint32_t* a, const uint32_t* b) {
    asm volatile("mma.sync.aligned.m16n8k16.row.col.f32.bf16.bf16.f32 "
        "{%0,%1,%2,%3}, {%4,%5,%6,%7}, {%8,%9}, {%0,%1,%2,%3};"
        : "+f"(c[0]), "+f"(c[1]), "+f"(c[2]), "+f"(c[3])
        : "r"(a[0]), "r"(a[1]), "r"(a[2]), "r"(a[3]), "r"(b[0]), "r"(b[1]));
}

// x -> (hi, lo) bf16 pair, 4 floats per thread.
__global__ void cvt_pair(const float* __restrict__ x, __nv_bfloat16* __restrict__ hi,
                         __nv_bfloat16* __restrict__ lo, int n4) {
    int i = blockIdx.x * 256 + threadIdx.x;
    if (i >= n4) return;
    float4 v = reinterpret_cast<const float4*>(x)[i];
    float f[4] = {v.x, v.y, v.z, v.w};
    uint32_t hs[4], ls[4];
    #pragma unroll
    for (int j = 0; j < 4; ++j) {
        __nv_bfloat16 h = __float2bfloat16_rn(f[j]);
        hs[j] = (uint32_t)__bfloat16_as_ushort(h);
        ls[j] = (uint32_t)__bfloat16_as_ushort(
            __float2bfloat16_rn(f[j] - __bfloat162float(h)));
    }
    uint2 hv, lv;
    hv.x = hs[0] | (hs[1] << 16); hv.y = hs[2] | (hs[3] << 16);
    lv.x = ls[0] | (ls[1] << 16); lv.y = ls[2] | (ls[3] << 16);
    reinterpret_cast<uint2*>(hi)[i] = hv;
    reinterpret_cast<uint2*>(lo)[i] = lv;
}

// ============================================================================
// mmagemm: C[128·by+:128, 64·bx+:64] = A@B^T + bias, fp32 via bf16 hi/lo split.
// ============================================================================
__global__ __launch_bounds__(256) void mmagemm(
    const __nv_bfloat16* __restrict__ Ahi, const __nv_bfloat16* __restrict__ Alo,
    const __nv_bfloat16* __restrict__ Bhi, const __nv_bfloat16* __restrict__ Blo,
    const float* __restrict__ bias, float* __restrict__ C, int N, int K)
{
    __shared__ __align__(16) __nv_bfloat16 sAh[128][40];
    __shared__ __align__(16) __nv_bfloat16 sAl[128][40];
    __shared__ __align__(16) __nv_bfloat16 sBh[64][40];
    __shared__ __align__(16) __nv_bfloat16 sBl[64][40];
    int tid = threadIdx.x, lane = tid & 31, wid = tid >> 5;
    int bm = blockIdx.y * 128, bn = blockIdx.x * 64;
    int wm = (wid & 3) * 32, wn = (wid >> 2) * 32;

    float acc[2][4][4];
    #pragma unroll
    for (int mi = 0; mi < 2; ++mi)
        #pragma unroll
        for (int ni = 0; ni < 4; ++ni)
            #pragma unroll
            for (int j = 0; j < 4; ++j) acc[mi][ni][j] = 0.f;

    uint32_t sAh0 = smem_u32(sAh), sAl0 = smem_u32(sAl);
    uint32_t sBh0 = smem_u32(sBh), sBl0 = smem_u32(sBl);
    uint32_t aoff0 = ((wm + (lane & 15)) * 40 + ((lane & 16) >> 1)) * 2;
    uint32_t aoff1 = aoff0 + 16 * 40 * 2;
    uint32_t boff0 = ((wn + (lane & 7) + ((lane & 16) >> 1)) * 40 + ((lane & 8) ? 8 : 0)) * 2;
    uint32_t boff1 = boff0 + 16 * 40 * 2;

    for (int kk = 0; kk < K; kk += 32) {
        for (int c = tid; c < 512; c += 256) {
            int r = c >> 2, cg = (c & 3) << 3;
            *reinterpret_cast<uint4*>(&sAh[r][cg]) =
                *reinterpret_cast<const uint4*>(Ahi + LL(bm + r) * K + kk + cg);
            *reinterpret_cast<uint4*>(&sAl[r][cg]) =
                *reinterpret_cast<const uint4*>(Alo + LL(bm + r) * K + kk + cg);
        }
        {
            int r = tid >> 2, cg = (tid & 3) << 3;
            *reinterpret_cast<uint4*>(&sBh[r][cg]) =
                *reinterpret_cast<const uint4*>(Bhi + LL(bn + r) * K + kk + cg);
            *reinterpret_cast<uint4*>(&sBl[r][cg]) =
                *reinterpret_cast<const uint4*>(Blo + LL(bn + r) * K + kk + cg);
        }
        __syncthreads();
        #pragma unroll
        for (int k16 = 0; k16 < 2; ++k16) {
            uint32_t kb = (uint32_t)(k16 * 32);
            uint32_t ah[2][4], al[2][4], bh[4][2], bl[4][2], t[4];
            ldsm_x4(ah[0], sAh0 + aoff0 + kb);
            ldsm_x4(ah[1], sAh0 + aoff1 + kb);
            ldsm_x4(al[0], sAl0 + aoff0 + kb);
            ldsm_x4(al[1], sAl0 + aoff1 + kb);
            ldsm_x4(t, sBh0 + boff0 + kb);
            bh[0][0] = t[0]; bh[0][1] = t[1]; bh[1][0] = t[2]; bh[1][1] = t[3];
            ldsm_x4(t, sBh0 + boff1 + kb);
            bh[2][0] = t[0]; bh[2][1] = t[1]; bh[3][0] = t[2]; bh[3][1] = t[3];
            ldsm_x4(t, sBl0 + boff0 + kb);
            bl[0][0] = t[0]; bl[0][1] = t[1]; bl[1][0] = t[2]; bl[1][1] = t[3];
            ldsm_x4(t, sBl0 + boff1 + kb);
            bl[2][0] = t[0]; bl[2][1] = t[1]; bl[3][0] = t[2]; bl[3][1] = t[3];
            #pragma unroll
            for (int mi = 0; mi < 2; ++mi)
                #pragma unroll
                for (int ni = 0; ni < 4; ++ni) {
                    mma16816(acc[mi][ni], ah[mi], bh[ni]);
                    mma16816(acc[mi][ni], ah[mi], bl[ni]);
                    mma16816(acc[mi][ni], al[mi], bh[ni]);
                }
        }
        __syncthreads();
    }

    int g = lane >> 2, tq = lane & 3;
    #pragma unroll
    for (int mi = 0; mi < 2; ++mi)
        #pragma unroll
        for (int ni = 0; ni < 4; ++ni) {
            int row0 = bm + wm + mi * 16 + g;
            int col = bn + wn + ni * 8 + tq * 2;
            float b0 = bias[col], b1 = bias[col + 1];
            C[LL row0 * N + col]           = acc[mi][ni][0] + b0;
            C[LL row0 * N + col + 1]       = acc[mi][ni][1] + b1;
            C[LL(row0 + 8) * N + col]      = acc[mi][ni][2] + b0;
            C[LL(row0 + 8) * N + col + 1]  = acc[mi][ni][3] + b1;
        }
}

// ============================== misc kernels ================================

// Two-phase mean: partials over 128-row l-chunks, then combine.
__global__ void mean_part(const float* __restrict__ hidden, float* __restrict__ pc) {
    int d = blockIdx.x * 256 + threadIdx.x;   // 4 x-blocks
    int b = blockIdx.y, z = blockIdx.z;       // 8 x 8
    const float* p = hidden + LL b * 1048576 + LL z * 131072 + d;
    float s = 0.f;
    #pragma unroll 8
    for (int l = 0; l < 128; ++l) s += p[LL l * 1024];
    pc[(z * 8 + b) * 1024 + d] = s;
}

__global__ void mean_comb(const float* __restrict__ pc, float* __restrict__ ctx) {
    int i = blockIdx.x * 256 + threadIdx.x;   // 32 blocks -> 8192
    int b = i >> 10, d = i & 1023;
    float s = 0.f;
    #pragma unroll
    for (int z = 0; z < 8; ++z) s += pc[(z * 8 + b) * 1024 + d];
    ctx[i] = s * (1.0f / 1024.0f);
}

__global__ void copy_to_buf(const float* __restrict__ tok, float* __restrict__ buf, int slot) {
    int b = blockIdx.x;
    int d = blockIdx.y * 256 + threadIdx.x;
    buf[LL(b * 32 + slot) * 1024 + d] = tok[b * 1024 + d];
}

// Scalar GEMM (small phase-C GEMMs only).
__global__ __launch_bounds__(256) void sgemm(
    const float* __restrict__ A, const float* __restrict__ B,
    const float* __restrict__ bias, float* __restrict__ C,
    int M, int N, int K)
{
    __shared__ __align__(16) float As[16][128];
    __shared__ __align__(16) float Bs[16][64];
    int tid = threadIdx.x;
    int tx = tid & 15, ty = tid >> 4;
    int bm = blockIdx.y * 128, bn = blockIdx.x * 64;
    float acc[8][4];
    #pragma unroll
    for (int i = 0; i < 8; ++i)
        #pragma unroll
        for (int j = 0; j < 4; ++j) acc[i][j] = 0.f;

    for (int kk = 0; kk < K; kk += 16) {
        #pragma unroll
        for (int s = tid; s < 512; s += 256) {
            int r = s >> 2, c = (s & 3) << 2;
            int gr = bm + r;
            float4 v = make_float4(0.f, 0.f, 0.f, 0.f);
            if (gr < M) v = *reinterpret_cast<const float4*>(A + LL gr * K + kk + c);
            As[c][r] = v.x; As[c + 1][r] = v.y; As[c + 2][r] = v.z; As[c + 3][r] = v.w;
        }
        {
            int r = tid >> 2, c = (tid & 3) << 2;
            float4 v = *reinterpret_cast<const float4*>(B + LL(bn + r) * K + kk + c);
            Bs[c][r] = v.x; Bs[c + 1][r] = v.y; Bs[c + 2][r] = v.z; Bs[c + 3][r] = v.w;
        }
        __syncthreads();
        #pragma unroll
        for (int k = 0; k < 16; ++k) {
            float a[8], bb[4];
            #pragma unroll
            for (int i = 0; i < 8; ++i) a[i] = As[k][ty * 8 + i];
            #pragma unroll
            for (int j = 0; j < 4; ++j) bb[j] = Bs[k][tx * 4 + j];
            #pragma unroll
            for (int i = 0; i < 8; ++i)
                #pragma unroll
                for (int j = 0; j < 4; ++j) acc[i][j] += a[i] * bb[j];
        }
        __syncthreads();
    }
    #pragma unroll
    for (int i = 0; i < 8; ++i) {
        int row = bm + ty * 8 + i;
        if (row < M) {
            float* cr = C + LL row * N + bn + tx * 4;
            #pragma unroll
            for (int j = 0; j < 4; ++j) cr[j] = acc[i][j] + bias[bn + tx * 4 + j];
        }
    }
}

// out[b,n] = A[b,:K].W[n,:K] + bias[n], 8 rows, warp per n (Phase A tok0 only).
__global__ __launch_bounds__(256) void smallgemm8(
    const float* __restrict__ A, int K,
    const float* __restrict__ W, const float* __restrict__ bias,
    float* __restrict__ out, int N)
{
    __shared__ __align__(16) float As[8192];
    int tid = threadIdx.x, lane = tid & 31, w = tid >> 5;
    int n = blockIdx.x * 8 + w;
    float acc[8];
    #pragma unroll
    for (int b = 0; b < 8; ++b) acc[b] = 0.f;
    for (int kk = 0; kk < K; kk += 1024) {
        for (int i = tid; i < 8192; i += 256) {
            int b = i >> 10, k = i & 1023;
            As[i] = A[LL b * K + kk + k];
        }
        __syncthreads();
        const float4* wr = reinterpret_cast<const float4*>(W + LL n * K + kk);
        for (int k4 = lane; k4 < 256; k4 += 32) {
            float4 wv = wr[k4];
            #pragma unroll
            for (int b = 0; b < 8; ++b) {
                float4 av = reinterpret_cast<const float4*>(As + b * 1024)[k4];
                acc[b] += wv.x * av.x + wv.y * av.y + wv.z * av.z + wv.w * av.w;
            }
        }
        __syncthreads();
    }
    #pragma unroll
    for (int off = 16; off; off >>= 1)
        #pragma unroll
        for (int b = 0; b < 8; ++b) acc[b] += __shfl_down_sync(0xffffffffu, acc[b], off);
    if (lane == 0) {
        float bv = bias[n];
        #pragma unroll
        for (int b = 0; b < 8; ++b) out[b * N + n] = acc[b] + bv;
    }
}

// In-place LayerNorm of 8 rows x 1024 staged in smem. blockDim == 256.
__device__ __forceinline__ void ln_inplace(float* sA, const float* g,
                                           const float* bv, float* st) {
    int tid = threadIdx.x, lane = tid & 31, w = tid >> 5;
    float s = 0.f;
    #pragma unroll
    for (int c = lane; c < 1024; c += 32) s += sA[w * 1024 + c];
    #pragma unroll
    for (int o = 16; o; o >>= 1) s += __shfl_xor_sync(0xffffffffu, s, o);
    float mean = s * (1.0f / 1024.0f);
    float v = 0.f;
    #pragma unroll
    for (int c = lane; c < 1024; c += 32) { float d = sA[w * 1024 + c] - mean; v += d * d; }
    #pragma unroll
    for (int o = 16; o; o >>= 1) v += __shfl_xor_sync(0xffffffffu, v, o);
    if (lane == 0) { st[w] = mean; st[8 + w] = rsqrtf(v * (1.0f / 1024.0f) + 1e-5f); }
    __syncthreads();
    for (int idx = tid; idx < 8192; idx += 256) {
        int r = idx >> 10, d = idx & 1023;
        sA[idx] = (sA[idx] - st[r]) * st[8 + r] * g[d] + bv[d];
    }
    __syncthreads();
}

// K0: (optional LN2 of pre) -> qkv. n<1024 -> q; else kvb slot step-1.
__global__ __launch_bounds__(256) void qkv_ln(
    const float* __restrict__ pre, float* tok,
    const float* __restrict__ aiw, const float* __restrict__ aib,
    const float* __restrict__ g2, const float* __restrict__ b2v,
    float* __restrict__ q, float* __restrict__ kvb, float* __restrict__ buf,
    int step, int do_ln)
{
    __shared__ __align__(16) float sA[8192];
    __shared__ float st[16];
    int tid = threadIdx.x, lane = tid & 31, w = tid >> 5;
    int bid = blockIdx.x;
    const float* src = do_ln ? pre : tok;
    for (int i = tid; i < 8192; i += 256) sA[i] = src[i];
    __syncthreads();
    if (do_ln) {
        ln_inplace(sA, g2, b2v, st);
        if (bid == 0) {
            for (int i = tid; i < 8192; i += 256) {
                tok[i] = sA[i];
                int b = i >> 10, d = i & 1023;
                buf[LL(b * 32 + step - 1) * 1024 + d] = sA[i];
            }
        }
    }
    int n = bid * 8 + w;
    const float4* wr = reinterpret_cast<const float4*>(aiw + LL n * 1024);
    float acc[8];
    #pragma unroll
    for (int b = 0; b < 8; ++b) acc[b] = 0.f;
    for (int k4 = lane; k4 < 256; k4 += 32) {
        float4 wv = wr[k4];
        #pragma unroll
        for (int b = 0; b < 8; ++b) {
            float4 av = reinterpret_cast<const float4*>(sA + b * 1024)[k4];
            acc[b] += wv.x * av.x + wv.y * av.y + wv.z * av.z + wv.w * av.w;
        }
    }
    #pragma unroll
    for (int off = 16; off; off >>= 1)
        #pragma unroll
        for (int b = 0; b < 8; ++b) acc[b] += __shfl_down_sync(0xffffffffu, acc[b], off);
    if (lane == 0) {
        float bv = aib[n];
        #pragma unroll
        for (int b = 0; b < 8; ++b) {
            float v = acc[b] + bv;
            if (n < 1024) q[b * 1024 + n] = v;
            else kvb[LL(b * 32 + step - 1) * 2048 + (n - 1024)] = v;
        }
    }
}

// K1a: split-K partial attention. 512 blocks = (b, h, p) with p in [0,4).
// Each block: scores for its key range, local max m / sum S, unnormalized
// weighted-V partial -> po[(bh*4+p)*64 + d], pms[(bh*4+p)*2] = {m, S}.
__global__ __launch_bounds__(256) void attn_part(
    const float* __restrict__ q, const float* __restrict__ qkvh,
    const float* __restrict__ kvb, float* __restrict__ po,
    float* __restrict__ pms, int Lk)
{
    int bid = blockIdx.x;
    int b = bid >> 6, h = (bid >> 2) & 15, p = bid & 3;
    int chunk = (Lk + 3) >> 2;
    int j0 = p * chunk;
    int j1 = j0 + chunk; if (j1 > Lk) j1 = Lk;
    int cnt = j1 - j0;
    __shared__ __align__(16) float sq[64];
    __shared__ float sc[272];
    __shared__ float red[256];
    __shared__ float part[8][64];
    int tid = threadIdx.x;
    if (tid < 64) sq[tid] = q[b * 1024 + h * 64 + tid];
    __syncthreads();

    float lmax = -1e30f;
    for (int jj = tid; jj < cnt; jj += 256) {
        int j = j0 + jj;
        const float* kr = (j < 1024)
            ? qkvh + LL(b * 1024 + j) * 3072 + 1024 + h * 64
            : kvb + LL(b * 32 + j - 1024) * 2048 + h * 64;
        const float4* k4 = reinterpret_cast<const float4*>(kr);
        const float4* q4 = reinterpret_cast<const float4*>(sq);
        float s = 0.f;
        #pragma unroll
        for (int d = 0; d < 16; ++d) {
            float4 kv = k4[d], qv = q4[d];
            s += kv.x * qv.x + kv.y * qv.y + kv.z * qv.z + kv.w * qv.w;
        }
        s *= 0.125f;
        sc[jj] = s;
        lmax = fmaxf(lmax, s);
    }
    red[tid] = lmax; __syncthreads();
    for (int o = 128; o; o >>= 1) { if (tid < o) red[tid] = fmaxf(red[tid], red[tid + o]); __syncthreads(); }
    float m = red[0];
    __syncthreads();
    float lsum = 0.f;
    for (int jj = tid; jj < cnt; jj += 256) { float e = __expf(sc[jj] - m); sc[jj] = e; lsum += e; }
    red[tid] = lsum; __syncthreads();
    for (int o = 128; o; o >>= 1) { if (tid < o) red[tid] += red[tid + o]; __syncthreads(); }
    float Ssum = red[0];

    int g = tid >> 5, d0 = (tid & 31) * 2;
    float ax = 0.f, ay = 0.f;
    for (int jj = g; jj < cnt; jj += 8) {
        int j = j0 + jj;
        const float* vr = (j < 1024)
            ? qkvh + LL(b * 1024 + j) * 3072 + 2048 + h * 64
            : kvb + LL(b * 32 + j - 1024) * 2048 + 1024 + h * 64;
        float2 v = *reinterpret_cast<const float2*>(vr + d0);
        float e = sc[jj];
        ax += e * v.x; ay += e * v.y;
    }
    part[g][d0] = ax; part[g][d0 + 1] = ay;
    __syncthreads();
    int idx = ((b * 16 + h) * 4 + p);
    if (tid < 64) {
        float s = 0.f;
        #pragma unroll
        for (int gg = 0; gg < 8; ++gg) s += part[gg][tid];
        po[idx * 64 + tid] = s;   // unnormalized (local max m)
    }
    if (tid == 0) { pms[idx * 2] = m; pms[idx * 2 + 1] = Ssum; }
}

// K1b: combine 4 partials per (b,h). 128 blocks x 64 threads.
__global__ void attn_comb(const float* __restrict__ po,
                          const float* __restrict__ pms, float* __restrict__ ao)
{
    int bh = blockIdx.x, d = threadIdx.x;
    float ms[4], ss[4];
    float M = -1e30f;
    #pragma unroll
    for (int p = 0; p < 4; ++p) {
        ms[p] = pms[(bh * 4 + p) * 2];
        ss[p] = pms[(bh * 4 + p) * 2 + 1];
        M = fmaxf(M, ms[p]);
    }
    float S = 0.f, o = 0.f;
    #pragma unroll
    for (int p = 0; p < 4; ++p) {
        float w = __expf(ms[p] - M);
        S += ss[p] * w;
        o += po[(bh * 4 + p) * 64 + d] * w;
    }
    ao[bh * 64 + d] = o / S;
}

// K2: tmp = ao @ aow^T + aob + tok (residual). 128 blocks.
__global__ __launch_bounds__(256) void outproj_res(
    const float* __restrict__ ao, const float* __restrict__ aow,
    const float* __restrict__ aob, const float* __restrict__ tok,
    float* __restrict__ tmp)
{
    __shared__ __align__(16) float sA[8192];
    int tid = threadIdx.x, lane = tid & 31, w = tid >> 5;
    for (int i = tid; i < 8192; i += 256) sA[i] = ao[i];
    __syncthreads();
    int n = blockIdx.x * 8 + w;
    const float4* wr = reinterpret_cast<const float4*>(aow + LL n * 1024);
    float acc[8];
    #pragma unroll
    for (int b = 0; b < 8; ++b) acc[b] = 0.f;
    for (int k4 = lane; k4 < 256; k4 += 32) {
        float4 wv = wr[k4];
        #pragma unroll
        for (int b = 0; b < 8; ++b) {
            float4 av = reinterpret_cast<const float4*>(sA + b * 1024)[k4];
            acc[b] += wv.x * av.x + wv.y * av.y + wv.z * av.z + wv.w * av.w;
        }
    }
    #pragma unroll
    for (int off = 16; off; off >>= 1)
        #pragma unroll
        for (int b = 0; b < 8; ++b) acc[b] += __shfl_down_sync(0xffffffffu, acc[b], off);
    if (lane == 0) {
        float bv = aob[n];
        #pragma unroll
        for (int b = 0; b < 8; ++b)
            tmp[b * 1024 + n] = acc[b] + bv + tok[b * 1024 + n];
    }
}

// K3: LN1(tmp) in-block -> FFN1 + gelu -> h1. bid 0 publishes tokl.
__global__ __launch_bounds__(256) void ffn1_ln(
    const float* __restrict__ tmp,
    const float* __restrict__ g1, const float* __restrict__ b1v,
    const float* __restrict__ fw1, const float* __restrict__ fb1,
    float* __restrict__ h1, float* __restrict__ tokl)
{
    __shared__ __align__(16) float sA[8192];
    __shared__ float st[16];
    int tid = threadIdx.x, lane = tid & 31, w = tid >> 5;
    int bid = blockIdx.x;
    for (int i = tid; i < 8192; i += 256) sA[i] = tmp[i];
    __syncthreads();
    ln_inplace(sA, g1, b1v, st);
    if (bid == 0)
        for (int i = tid; i < 8192; i += 256) tokl[i] = sA[i];
    int n = bid * 8 + w;
    const float4* wr = reinterpret_cast<const float4*>(fw1 + LL n * 1024);
    float acc[8];
    #pragma unroll
    for (int b = 0; b < 8; ++b) acc[b] = 0.f;
    for (int k4 = lane; k4 < 256; k4 += 32) {
        float4 wv = wr[k4];
        #pragma unroll
        for (int b = 0; b < 8; ++b) {
            float4 av = reinterpret_cast<const float4*>(sA + b * 1024)[k4];
            acc[b] += wv.x * av.x + wv.y * av.y + wv.z * av.z + wv.w * av.w;
        }
    }
    #pragma unroll
    for (int off = 16; off; off >>= 1)
        #pragma unroll
        for (int b = 0; b < 8; ++b) acc[b] += __shfl_down_sync(0xffffffffu, acc[b], off);
    if (lane == 0) {
        float bv = fb1[n];
        #pragma unroll
        for (int b = 0; b < 8; ++b) h1[b * 2048 + n] = geluf(acc[b] + bv);
    }
}

// K4: tmp2 = h1 @ fw2^T + fb2 + tokl (residual). 128 blocks.
__global__ __launch_bounds__(256) void ffn2_res(
    const float* __restrict__ h1, const float* __restrict__ fw2,
    const float* __restrict__ fb2, const float* __restrict__ tokl,
    float* __restrict__ tmp2)
{
    __shared__ __align__(16) float sA[8192];
    int tid = threadIdx.x, lane = tid & 31, w = tid >> 5;
    int n = blockIdx.x * 8 + w;
    float acc[8];
    #pragma unroll
    for (int b = 0; b < 8; ++b) acc[b] = 0.f;
    for (int kk = 0; kk < 2048; kk += 1024) {
        for (int i = tid; i < 8192; i += 256) {
            int b = i >> 10, k = i & 1023;
            sA[i] = h1[b * 2048 + kk + k];
        }
        __syncthreads();
        const float4* wr = reinterpret_cast<const float4*>(fw2 + LL n * 2048 + kk);
        for (int k4 = lane; k4 < 256; k4 += 32) {
            float4 wv = wr[k4];
            #pragma unroll
            for (int b = 0; b < 8; ++b) {
                float4 av = reinterpret_cast<const float4*>(sA + b * 1024)[k4];
                acc[b] += wv.x * av.x + wv.y * av.y + wv.z * av.z + wv.w * av.w;
            }
        }
        __syncthreads();
    }
    #pragma unroll
    for (int off = 16; off; off >>= 1)
        #pragma unroll
        for (int b = 0; b < 8; ++b) acc[b] += __shfl_down_sync(0xffffffffu, acc[b], off);
    if (lane == 0) {
        float bv = fb2[n];
        #pragma unroll
        for (int b = 0; b < 8; ++b)
            tmp2[b * 1024 + n] = acc[b] + bv + tokl[b * 1024 + n];
    }
}

__global__ void ln8(const float* __restrict__ x, const float* __restrict__ gg,
                    const float* __restrict__ bb, float* __restrict__ out,
                    float* __restrict__ buf, int slot)
{
    int b = blockIdx.x, tid = threadIdx.x;
    __shared__ float red[256];
    const float* xr = x + b * 1024;
    float vals[4]; float s = 0.f;
    #pragma unroll
    for (int i = 0; i < 4; ++i) { vals[i] = xr[tid + 256 * i]; s += vals[i]; }
    red[tid] = s; __syncthreads();
    for (int o = 128; o; o >>= 1) { if (tid < o) red[tid] += red[tid + o]; __syncthreads(); }
    float mean = red[0] * (1.0f / 1024.0f);
    __syncthreads();
    float v = 0.f;
    #pragma unroll
    for (int i = 0; i < 4; ++i) { float dd = vals[i] - mean; v += dd * dd; }
    red[tid] = v; __syncthreads();
    for (int o = 128; o; o >>= 1) { if (tid < o) red[tid] += red[tid + o]; __syncthreads(); }
    float inv = rsqrtf(red[0] * (1.0f / 1024.0f) + 1e-5f);
    #pragma unroll
    for (int i = 0; i < 4; ++i) {
        int d = tid + 256 * i;
        float y = (vals[i] - mean) * inv * gg[d] + bb[d];
        out[b * 1024 + d] = y;
        if (buf) buf[LL(b * 32 + slot) * 1024 + d] = y;
    }
}

__global__ void ln_big(const float* __restrict__ hidden, const float* __restrict__ att,
                       const float* __restrict__ gg, const float* __restrict__ bb,
                       float* __restrict__ out)
{
    int l = blockIdx.x, tid = threadIdx.x;
    __shared__ float red[256];
    const float* hr = hidden + LL l * 1024;
    const float* ar = att + LL l * 1024;
    float vals[4]; float s = 0.f;
    #pragma unroll
    for (int i = 0; i < 4; ++i) { vals[i] = hr[tid + 256 * i] + ar[tid + 256 * i]; s += vals[i]; }
    red[tid] = s; __syncthreads();
    for (int o = 128; o; o >>= 1) { if (tid < o) red[tid] += red[tid + o]; __syncthreads(); }
    float mean = red[0] * (1.0f / 1024.0f);
    __syncthreads();
    float v = 0.f;
    #pragma unroll
    for (int i = 0; i < 4; ++i) { float dd = vals[i] - mean; v += dd * dd; }
    red[tid] = v; __syncthreads();
    for (int o = 128; o; o >>= 1) { if (tid < o) red[tid] += red[tid + o]; __syncthreads(); }
    float inv = rsqrtf(red[0] * (1.0f / 1024.0f) + 1e-5f);
    #pragma unroll
    for (int i = 0; i < 4; ++i) {
        int d = tid + 256 * i;
        out[LL l * 1024 + d] = (vals[i] - mean) * inv * gg[d] + bb[d];
    }
}

__global__ __launch_bounds__(256) void comp_kernel(
    const float* __restrict__ comp_q, const float* __restrict__ thoughts,
    float* __restrict__ ssum)
{
    int b = blockIdx.x >> 3, c = blockIdx.x & 7;
    __shared__ float sc[32];
    __shared__ float pr[32];
    int tid = threadIdx.x, lane = tid & 31, w = tid >> 5;
    const float* qr = comp_q + c * 1024;
    #pragma unroll
    for (int si = 0; si < 4; ++si) {
        int s = w * 4 + si;
        const float* t = thoughts + LL(b * 32 + s) * 1024;
        float acc = 0.f;
        for (int k = lane; k < 1024; k += 32) acc += qr[k] * t[k];
        #pragma unroll
        for (int o = 16; o; o >>= 1) acc += __shfl_down_sync(0xffffffffu, acc, o);
        if (lane == 0) sc[s] = acc * (1.0f / 32.0f);
    }
    __syncthreads();
    if (tid == 0) {
        float m = -1e30f;
        for (int s = 0; s < 32; ++s) m = fmaxf(m, sc[s]);
        float S = 0.f;
        for (int s = 0; s < 32; ++s) { float p = __expf(sc[s] - m); pr[s] = p; S += p; }
        float iv = 1.0f / S;
        for (int s = 0; s < 32; ++s) pr[s] *= iv;
    }
    __syncthreads();
    for (int d = tid; d < 1024; d += 256) {
        float acc = 0.f;
        #pragma unroll
        for (int s = 0; s < 32; ++s) acc += pr[s] * thoughts[LL(b * 32 + s) * 1024 + d];
        ssum[LL(b * 8 + c) * 1024 + d] = acc;
    }
}

__global__ __launch_bounds__(256) void final_attn(
    const float* __restrict__ qkvh, const float* __restrict__ kvs,
    float* __restrict__ o)
{
    int tid = threadIdx.x, lane = tid & 31, w = tid >> 5;
    int pair = blockIdx.x * 8 + w;
    int l = pair >> 4, h = pair & 15;
    int b = l >> 10;
    float2 qv = reinterpret_cast<const float2*>(qkvh + LL l * 3072 + h * 64)[lane];
    float s[8];
    #pragma unroll
    for (int ks = 0; ks < 8; ++ks) {
        float2 kv = reinterpret_cast<const float2*>(kvs + LL(b * 8 + ks) * 2048 + h * 64)[lane];
        float p = qv.x * kv.x + qv.y * kv.y;
        #pragma unroll
        for (int off = 16; off; off >>= 1) p += __shfl_xor_sync(0xffffffffu, p, off);
        s[ks] = p * 0.125f;
    }
    float m = s[0];
    #pragma unroll
    for (int ks = 1; ks < 8; ++ks) m = fmaxf(m, s[ks]);
    float sum = 0.f;
    #pragma unroll
    for (int ks = 0; ks < 8; ++ks) { s[ks] = __expf(s[ks] - m); sum += s[ks]; }
    float inv = 1.0f / sum;
    float o0 = 0.f, o1 = 0.f;
    #pragma unroll
    for (int ks = 0; ks < 8; ++ks) {
        float2 vv = reinterpret_cast<const float2*>(kvs + LL(b * 8 + ks) * 2048 + 1024 + h * 64)[lane];
        o0 += s[ks] * vv.x; o1 += s[ks] * vv.y;
    }
    float2 ov; ov.x = o0 * inv; ov.y = o1 * inv;
    reinterpret_cast<float2*>(o + LL l * 1024 + h * 64)[lane] = ov;
}

extern "C" void kernel_launch(void* const* d_in, const int* in_sizes, int n_in,
                              void* d_out, int out_size) {
    (void)in_sizes; (void)n_in; (void)out_size;
    const float* hidden = (const float*)d_in[0];
    const float* tpw    = (const float*)d_in[1];
    const float* tpb    = (const float*)d_in[2];
    const float* ln1g   = (const float*)d_in[3];
    const float* ln1b   = (const float*)d_in[4];
    const float* ln2g   = (const float*)d_in[5];
    const float* ln2b   = (const float*)d_in[6];
    const float* aiw    = (const float*)d_in[7];
    const float* aib    = (const float*)d_in[8];
    const float* aow    = (const float*)d_in[9];
    const float* aob    = (const float*)d_in[10];
    const float* fw1    = (const float*)d_in[11];
    const float* fb1    = (const float*)d_in[12];
    const float* fw2    = (const float*)d_in[13];
    const float* fb2    = (const float*)d_in[14];
    const float* cq     = (const float*)d_in[15];
    const float* cw     = (const float*)d_in[16];
    const float* cb     = (const float*)d_in[17];
    float* out = (float*)d_out;

    float* S;
    cudaGetSymbolAddress((void**)&S, g_scratch);
    __nv_bfloat16* BF;
    cudaGetSymbolAddress((void**)&BF, g_bf);

    float* QKVH = S + OFF_QKVH;
    float* BUF  = S + OFF_BUF;
    float* KVB  = S + OFF_KVB;
    float* CTX  = S + OFF_CTX;
    float* TOK  = S + OFF_TOK;
    float* TMP  = S + OFF_TMP;
    float* TMP2 = S + OFF_TMP2;
    float* H1   = S + OFF_H1;
    float* Q    = S + OFF_Q;
    float* AO   = S + OFF_AO;
    float* KVS  = S + OFF_KVS;
    float* SSUM = S + OFF_SSUM;
    float* PO   = S + OFF_PO;
    float* PMS  = S + OFF_PMS;
    float* PC   = S + OFF_PC;
    float* O    = S + OFF_O;
    float* ATT  = S + OFF_ATT;
    float* SUMM = out + LL 8192 * 1024;   // (8,8,1024) tail of output
    float* TOKL = CTX;                    // ctx is dead after tok0

    // Phase A: operand conversion + two-phase mean + tensor-core QKV.
    cvt_pair<<<8192, 256>>>(hidden, BF + BHHI, BF + BHLO, 2097152);
    cvt_pair<<<3072, 256>>>(aiw, BF + BWIHI, BF + BWILO, 786432);
    cvt_pair<<<1024, 256>>>(aow, BF + BWOHI, BF + BWOLO, 262144);
    mean_part<<<dim3(4, 8, 8), 256>>>(hidden, PC);
    mean_comb<<<32, 256>>>(PC, CTX);
    smallgemm8<<<128, 256>>>(CTX, 1024, tpw, tpb, TOK, 1024);
    copy_to_buf<<<dim3(8, 4), 256>>>(TOK, BUF, 0);
    mmagemm<<<dim3(48, 64), 256>>>(BF + BHHI, BF + BHLO, BF + BWIHI, BF + BWILO,
                                   aib, QKVH, 3072, 1024);

    // Phase B: 31 steps x 6 kernels (split-K attention)
    for (int i = 1; i < 32; ++i) {
        qkv_ln<<<384, 256>>>(TMP2, TOK, aiw, aib, ln2g, ln2b, Q, KVB, BUF, i, i > 1);
        attn_part<<<512, 256>>>(Q, QKVH, KVB, PO, PMS, 1024 + i);
        attn_comb<<<128, 64>>>(PO, PMS, AO);
        outproj_res<<<128, 256>>>(AO, aow, aob, TOK, TMP);
        ffn1_ln<<<256, 256>>>(TMP, ln1g, ln1b, fw1, fb1, H1, TOKL);
        ffn2_res<<<128, 256>>>(H1, fw2, fb2, TOKL, TMP2);
    }
    ln8<<<8, 256>>>(TMP2, ln2g, ln2b, TOK, BUF, 31);

    // Phase C
    comp_kernel<<<64, 256>>>(cq, BUF, SSUM);
    sgemm<<<dim3(16, 1), 256>>>(SSUM, cw, cb, SUMM, 64, 1024, 1024);
    sgemm<<<dim3(32, 1), 256>>>(SUMM, aiw + LL 1024 * 1024, aib + 1024, KVS, 64, 2048, 1024);
    final_attn<<<16384, 256>>>(QKVH, KVS, O);
    cvt_pair<<<8192, 256>>>(O, BF + BOHI, BF + BOLO, 2097152);
    mmagemm<<<dim3(16, 64), 256>>>(BF + BOHI, BF + BOLO, BF + BWOHI, BF + BWOLO,
                                   aob, ATT, 1024, 1024);
    ln_big<<<8192, 256>>>(hidden, ATT, ln1g, ln1b, out);
}